// round 1
// baseline (speedup 1.0000x reference)
#include <cuda_runtime.h>
#include <math.h>

#define B_ 2
#define T_ 2048
#define C_ 1024
#define H_ 16
#define D_ 64
#define M_ (B_*T_)   // 4096 rows

// Scratch (allocation-free): Q, K, V, attention-out, each 16 MB fp32.
__device__ float g_q[M_*C_];
__device__ float g_k[M_*C_];
__device__ float g_v[M_*C_];
__device__ float g_o[M_*C_];

// ---------------------------------------------------------------------------
// Tiled fp32 GEMM with bias:  C[M,N] = A[M,K] @ W[K,N] + bias[N]
// 128x128 block tile, BK=16, 256 threads, 8x8 register micro-tile.
// asel: 0 -> A = Aext, 1 -> A = g_o
// osel: 0 -> g_q, 1 -> g_k, 2 -> g_v, 3 -> Oext
// ---------------------------------------------------------------------------
#define BM 128
#define BN 128
#define BK 16
#define TM 8
#define TN 8

__global__ __launch_bounds__(256) void gemm_bias_kernel(
    const float* __restrict__ Aext, const float* __restrict__ W,
    const float* __restrict__ bias, float* __restrict__ Oext,
    int asel, int osel, int M, int N, int K)
{
    const float* A = asel ? (const float*)g_o : Aext;
    float* Cm = (osel == 0) ? g_q : (osel == 1) ? g_k : (osel == 2) ? g_v : Oext;

    __shared__ float As[BK][BM + 4];   // A stored transposed: As[k][m]
    __shared__ float Ws[BK][BN];

    int tid  = threadIdx.x;
    int brow = blockIdx.y * BM;
    int bcol = blockIdx.x * BN;

    float acc[TM][TN];
    #pragma unroll
    for (int i = 0; i < TM; i++)
        #pragma unroll
        for (int j = 0; j < TN; j++) acc[i][j] = 0.f;

    int ty = tid >> 4;      // 0..15
    int tx = tid & 15;      // 0..15

    for (int k0 = 0; k0 < K; k0 += BK) {
        // Load A tile: BM x BK = 2048 floats (512 float4), 2 per thread.
        #pragma unroll
        for (int l = 0; l < 2; l++) {
            int f4 = tid + l * 256;          // 0..511
            int r  = f4 >> 2;                // 4 float4 per row (BK=16)
            int c4 = (f4 & 3) * 4;
            float4 v = *(const float4*)&A[(size_t)(brow + r) * K + k0 + c4];
            As[c4 + 0][r] = v.x;
            As[c4 + 1][r] = v.y;
            As[c4 + 2][r] = v.z;
            As[c4 + 3][r] = v.w;
        }
        // Load W tile: BK x BN = 2048 floats, 2 float4 per thread.
        #pragma unroll
        for (int l = 0; l < 2; l++) {
            int f4 = tid + l * 256;
            int r  = f4 >> 5;                // 32 float4 per row (BN=128)
            int c4 = (f4 & 31) * 4;
            *(float4*)&Ws[r][c4] = *(const float4*)&W[(size_t)(k0 + r) * N + bcol + c4];
        }
        __syncthreads();

        #pragma unroll
        for (int kk = 0; kk < BK; kk++) {
            float a[TM], b[TN];
            #pragma unroll
            for (int i = 0; i < TM; i++) a[i] = As[kk][ty * TM + i];
            #pragma unroll
            for (int j = 0; j < TN; j++) b[j] = Ws[kk][tx * TN + j];
            #pragma unroll
            for (int i = 0; i < TM; i++)
                #pragma unroll
                for (int j = 0; j < TN; j++)
                    acc[i][j] += a[i] * b[j];
        }
        __syncthreads();
    }

    #pragma unroll
    for (int i = 0; i < TM; i++) {
        int r = brow + ty * TM + i;
        #pragma unroll
        for (int j = 0; j < TN; j += 4) {
            int c = bcol + tx * TN + j;
            float4 o;
            o.x = acc[i][j + 0] + bias[c + 0];
            o.y = acc[i][j + 1] + bias[c + 1];
            o.z = acc[i][j + 2] + bias[c + 2];
            o.w = acc[i][j + 3] + bias[c + 3];
            *(float4*)&Cm[(size_t)r * N + c] = o;
        }
    }
}

// ---------------------------------------------------------------------------
// Flash attention with ALiBi + causal mask.
// grid = (T/QT, H, B), block = 128 threads. One thread per query row.
// Online softmax over 16-key chunks; K/V tiles of 64 keys staged in SMEM.
// ---------------------------------------------------------------------------
#define QT 128
#define KT 64

__global__ __launch_bounds__(128) void attn_kernel()
{
    __shared__ float Ks[KT][D_];
    __shared__ float Vs[KT][D_];

    int tid = threadIdx.x;
    int qi  = blockIdx.x * QT + tid;   // query index within T
    int h   = blockIdx.y;
    int b   = blockIdx.z;

    const float scale = 0.125f;                         // 1/sqrt(64)
    const float slope = exp2f(-0.5f * (float)(h + 1));  // ALiBi slope for this head

    float qreg[D_];
    const float* qptr = &g_q[((size_t)(b * T_ + qi)) * C_ + h * D_];
    #pragma unroll
    for (int d = 0; d < D_; d++) qreg[d] = qptr[d] * scale;

    float Oacc[D_];
    #pragma unroll
    for (int d = 0; d < D_; d++) Oacc[d] = 0.f;
    float mrun = -1e30f, lrun = 0.f;

    const int kend = blockIdx.x * QT + QT;   // causal horizon for this block

    for (int k0 = 0; k0 < kend; k0 += KT) {
        __syncthreads();
        // Cooperative load of K,V tile: 64x64 floats each; 8 float4 per thread per tensor.
        #pragma unroll
        for (int l = 0; l < 8; l++) {
            int f4 = tid + l * 128;          // 0..1023
            int r  = f4 >> 4;                // 16 float4 per row
            int c4 = (f4 & 15) * 4;
            size_t base = ((size_t)(b * T_ + k0 + r)) * C_ + h * D_ + c4;
            *(float4*)&Ks[r][c4] = *(const float4*)&g_k[base];
            *(float4*)&Vs[r][c4] = *(const float4*)&g_v[base];
        }
        __syncthreads();

        #pragma unroll 1
        for (int j0 = 0; j0 < KT; j0 += 16) {
            float s[16];
            float chmax = -1e30f;
            #pragma unroll
            for (int j = 0; j < 16; j++) {
                int kj = k0 + j0 + j;
                float acc = 0.f;
                #pragma unroll
                for (int d = 0; d < D_; d++) acc += qreg[d] * Ks[j0 + j][d];
                if (kj <= qi) acc += slope * (float)(kj - qi);   // ALiBi (<=0)
                else          acc = -1e30f;                      // causal mask
                s[j] = acc;
                chmax = fmaxf(chmax, acc);
            }
            float mnew = fmaxf(mrun, chmax);
            float corr = __expf(mrun - mnew);
            lrun *= corr;
            #pragma unroll
            for (int d = 0; d < D_; d++) Oacc[d] *= corr;
            #pragma unroll
            for (int j = 0; j < 16; j++) {
                float p = __expf(s[j] - mnew);
                lrun += p;
                #pragma unroll
                for (int d = 0; d < D_; d++) Oacc[d] += p * Vs[j0 + j][d];
            }
            mrun = mnew;
        }
    }

    float inv = 1.f / lrun;
    float* op = &g_o[((size_t)(b * T_ + qi)) * C_ + h * D_];
    #pragma unroll
    for (int d = 0; d < D_; d++) op[d] = Oacc[d] * inv;
}

// ---------------------------------------------------------------------------
extern "C" void kernel_launch(void* const* d_in, const int* in_sizes, int n_in,
                              void* d_out, int out_size)
{
    const float* x  = (const float*)d_in[0];
    const float* Wq = (const float*)d_in[1];
    const float* bq = (const float*)d_in[2];
    const float* Wk = (const float*)d_in[3];
    const float* bk = (const float*)d_in[4];
    const float* Wv = (const float*)d_in[5];
    const float* bv = (const float*)d_in[6];
    const float* Wo = (const float*)d_in[7];
    const float* bo = (const float*)d_in[8];
    float* out = (float*)d_out;

    dim3 gp(C_ / BN, M_ / BM);   // (8, 32)

    // QKV projections
    gemm_bias_kernel<<<gp, 256>>>(x, Wq, bq, nullptr, 0, 0, M_, C_, C_);
    gemm_bias_kernel<<<gp, 256>>>(x, Wk, bk, nullptr, 0, 1, M_, C_, C_);
    gemm_bias_kernel<<<gp, 256>>>(x, Wv, bv, nullptr, 0, 2, M_, C_, C_);

    // Attention
    attn_kernel<<<dim3(T_ / QT, H_, B_), 128>>>();

    // Output projection
    gemm_bias_kernel<<<gp, 256>>>(nullptr, Wo, bo, out, 1, 3, M_, C_, C_);
}

// round 2
// speedup vs baseline: 1.3931x; 1.3931x over previous
#include <cuda_runtime.h>
#include <stdint.h>
#include <math.h>

#define B_ 2
#define T_ 2048
#define C_ 1024
#define H_ 16
#define D_ 64
#define M_ (B_*T_)   // 4096 rows

// Scratch (allocation-free): Q, K, V, attention-out, each 16 MB fp32.
__device__ float g_q[M_*C_];
__device__ float g_k[M_*C_];
__device__ float g_v[M_*C_];
__device__ float g_o[M_*C_];

// ---------------------------------------------------------------------------
// TF32 tensor-core GEMM with bias: C[M,N] = A[M,K] @ W[K,N] + bias[N]
// 128x128 block tile, BK=32, 256 threads (8 warps, 2x4), warp tile 64x32,
// mma.sync.m16n8k8.tf32. SMEM strides picked for conflict-free frag loads.
// ---------------------------------------------------------------------------
#define BM 128
#define BN 128
#define BK 32
#define SA 36    // As row stride (uint32): frag banks = 4*(l>>2)+(l&3), bijective
#define SB 136   // Ws row stride (uint32): frag banks = 8*(l&3)+(l>>2), bijective

__device__ __forceinline__ uint32_t f2tf32(float x) {
    uint32_t u;
    asm("cvt.rna.tf32.f32 %0, %1;" : "=r"(u) : "f"(x));
    return u;
}

__device__ __forceinline__ void mma_tf32(float c[4],
    uint32_t a0, uint32_t a1, uint32_t a2, uint32_t a3,
    uint32_t b0, uint32_t b1)
{
    asm volatile(
        "mma.sync.aligned.m16n8k8.row.col.f32.tf32.tf32.f32 "
        "{%0,%1,%2,%3},{%4,%5,%6,%7},{%8,%9},{%0,%1,%2,%3};"
        : "+f"(c[0]), "+f"(c[1]), "+f"(c[2]), "+f"(c[3])
        : "r"(a0), "r"(a1), "r"(a2), "r"(a3), "r"(b0), "r"(b1));
}

__global__ __launch_bounds__(256) void gemm_tf32_kernel(
    const float* __restrict__ Aext, const float* __restrict__ W,
    const float* __restrict__ bias, float* __restrict__ Oext,
    int asel, int osel, int M, int N, int K)
{
    const float* A = asel ? (const float*)g_o : Aext;
    float* Cm = (osel == 0) ? g_q : (osel == 1) ? g_k : (osel == 2) ? g_v : Oext;

    __shared__ uint32_t As[BM][SA];
    __shared__ uint32_t Ws[BK][SB];

    const int tid  = threadIdx.x;
    const int lane = tid & 31;
    const int warp = tid >> 5;
    const int wr   = warp >> 2;      // 0..1  -> 64-row band
    const int wc   = warp & 3;       // 0..3  -> 32-col band
    const int brow = blockIdx.y * BM;
    const int bcol = blockIdx.x * BN;

    const int lg = lane >> 2;        // group id 0..7
    const int lt = lane & 3;         // thread-in-group 0..3

    float acc[4][4][4];
    #pragma unroll
    for (int mf = 0; mf < 4; mf++)
        #pragma unroll
        for (int nf = 0; nf < 4; nf++)
            #pragma unroll
            for (int r = 0; r < 4; r++) acc[mf][nf][r] = 0.f;

    for (int k0 = 0; k0 < K; k0 += BK) {
        // Load A tile (128x32): 1024 float4, 4 per thread. tf32-convert on store.
        #pragma unroll
        for (int l = 0; l < 4; l++) {
            int f4 = tid + l * 256;
            int r  = f4 >> 3;                 // 8 float4 per row
            int c4 = (f4 & 7) << 2;
            float4 v = *(const float4*)&A[(size_t)(brow + r) * K + k0 + c4];
            uint4 u = { f2tf32(v.x), f2tf32(v.y), f2tf32(v.z), f2tf32(v.w) };
            *(uint4*)&As[r][c4] = u;
        }
        // Load W tile (32x128): 1024 float4, 4 per thread.
        #pragma unroll
        for (int l = 0; l < 4; l++) {
            int f4 = tid + l * 256;
            int r  = f4 >> 5;                 // 32 float4 per row
            int c4 = (f4 & 31) << 2;
            float4 v = *(const float4*)&W[(size_t)(k0 + r) * N + bcol + c4];
            uint4 u = { f2tf32(v.x), f2tf32(v.y), f2tf32(v.z), f2tf32(v.w) };
            *(uint4*)&Ws[r][c4] = u;
        }
        __syncthreads();

        #pragma unroll
        for (int ks = 0; ks < 4; ks++) {
            const int kb = ks * 8;
            uint32_t bf[4][2];
            #pragma unroll
            for (int nf = 0; nf < 4; nf++) {
                int n = wc * 32 + nf * 8 + lg;
                bf[nf][0] = Ws[kb + lt][n];
                bf[nf][1] = Ws[kb + 4 + lt][n];
            }
            #pragma unroll
            for (int mf = 0; mf < 4; mf++) {
                int m0 = wr * 64 + mf * 16 + lg;
                uint32_t a0 = As[m0][kb + lt];
                uint32_t a1 = As[m0 + 8][kb + lt];
                uint32_t a2 = As[m0][kb + 4 + lt];
                uint32_t a3 = As[m0 + 8][kb + 4 + lt];
                #pragma unroll
                for (int nf = 0; nf < 4; nf++)
                    mma_tf32(acc[mf][nf], a0, a1, a2, a3, bf[nf][0], bf[nf][1]);
            }
        }
        __syncthreads();
    }

    // Epilogue: bias add, float2 stores.
    #pragma unroll
    for (int mf = 0; mf < 4; mf++) {
        int row0 = brow + wr * 64 + mf * 16 + lg;
        #pragma unroll
        for (int nf = 0; nf < 4; nf++) {
            int col = bcol + wc * 32 + nf * 8 + lt * 2;
            float bx = bias[col], by = bias[col + 1];
            float2 o0 = { acc[mf][nf][0] + bx, acc[mf][nf][1] + by };
            float2 o1 = { acc[mf][nf][2] + bx, acc[mf][nf][3] + by };
            *(float2*)&Cm[(size_t)row0 * N + col]       = o0;
            *(float2*)&Cm[(size_t)(row0 + 8) * N + col] = o1;
        }
    }
}

// ---------------------------------------------------------------------------
// Flash attention with ALiBi + causal mask.
// grid = (T/QT, H, B), block = 128 threads. One thread per query row.
// ---------------------------------------------------------------------------
#define QT 128
#define KT 64

__global__ __launch_bounds__(128) void attn_kernel()
{
    __shared__ float Ks[KT][D_];
    __shared__ float Vs[KT][D_];

    int tid = threadIdx.x;
    int qi  = blockIdx.x * QT + tid;
    int h   = blockIdx.y;
    int b   = blockIdx.z;

    const float scale = 0.125f;                         // 1/sqrt(64)
    const float slope = exp2f(-0.5f * (float)(h + 1));  // ALiBi slope

    float qreg[D_];
    const float* qptr = &g_q[((size_t)(b * T_ + qi)) * C_ + h * D_];
    #pragma unroll
    for (int d = 0; d < D_; d++) qreg[d] = qptr[d] * scale;

    float Oacc[D_];
    #pragma unroll
    for (int d = 0; d < D_; d++) Oacc[d] = 0.f;
    float mrun = -1e30f, lrun = 0.f;

    const int kend = blockIdx.x * QT + QT;

    for (int k0 = 0; k0 < kend; k0 += KT) {
        __syncthreads();
        #pragma unroll
        for (int l = 0; l < 8; l++) {
            int f4 = tid + l * 128;
            int r  = f4 >> 4;
            int c4 = (f4 & 15) * 4;
            size_t base = ((size_t)(b * T_ + k0 + r)) * C_ + h * D_ + c4;
            *(float4*)&Ks[r][c4] = *(const float4*)&g_k[base];
            *(float4*)&Vs[r][c4] = *(const float4*)&g_v[base];
        }
        __syncthreads();

        #pragma unroll 1
        for (int j0 = 0; j0 < KT; j0 += 16) {
            float s[16];
            float chmax = -1e30f;
            #pragma unroll
            for (int j = 0; j < 16; j++) {
                int kj = k0 + j0 + j;
                float acc = 0.f;
                #pragma unroll
                for (int d = 0; d < D_; d++) acc += qreg[d] * Ks[j0 + j][d];
                if (kj <= qi) acc += slope * (float)(kj - qi);
                else          acc = -1e30f;
                s[j] = acc;
                chmax = fmaxf(chmax, acc);
            }
            float mnew = fmaxf(mrun, chmax);
            float corr = __expf(mrun - mnew);
            lrun *= corr;
            #pragma unroll
            for (int d = 0; d < D_; d++) Oacc[d] *= corr;
            #pragma unroll
            for (int j = 0; j < 16; j++) {
                float p = __expf(s[j] - mnew);
                lrun += p;
                #pragma unroll
                for (int d = 0; d < D_; d++) Oacc[d] += p * Vs[j0 + j][d];
            }
            mrun = mnew;
        }
    }

    float inv = 1.f / lrun;
    float* op = &g_o[((size_t)(b * T_ + qi)) * C_ + h * D_];
    #pragma unroll
    for (int d = 0; d < D_; d++) op[d] = Oacc[d] * inv;
}

// ---------------------------------------------------------------------------
extern "C" void kernel_launch(void* const* d_in, const int* in_sizes, int n_in,
                              void* d_out, int out_size)
{
    const float* x  = (const float*)d_in[0];
    const float* Wq = (const float*)d_in[1];
    const float* bq = (const float*)d_in[2];
    const float* Wk = (const float*)d_in[3];
    const float* bk = (const float*)d_in[4];
    const float* Wv = (const float*)d_in[5];
    const float* bv = (const float*)d_in[6];
    const float* Wo = (const float*)d_in[7];
    const float* bo = (const float*)d_in[8];
    float* out = (float*)d_out;

    dim3 gp(C_ / BN, M_ / BM);   // (8, 32)

    gemm_tf32_kernel<<<gp, 256>>>(x, Wq, bq, nullptr, 0, 0, M_, C_, C_);
    gemm_tf32_kernel<<<gp, 256>>>(x, Wk, bk, nullptr, 0, 1, M_, C_, C_);
    gemm_tf32_kernel<<<gp, 256>>>(x, Wv, bv, nullptr, 0, 2, M_, C_, C_);

    attn_kernel<<<dim3(T_ / QT, H_, B_), 128>>>();

    gemm_tf32_kernel<<<gp, 256>>>(nullptr, Wo, bo, out, 1, 3, M_, C_, C_);
}

// round 3
// speedup vs baseline: 3.9850x; 2.8606x over previous
#include <cuda_runtime.h>
#include <stdint.h>
#include <math.h>

#define B_ 2
#define T_ 2048
#define C_ 1024
#define H_ 16
#define D_ 64
#define M_ (B_*T_)   // 4096 rows

// Scratch (allocation-free): Q, K, V, attention-out, each 16 MB fp32.
__device__ float g_q[M_*C_];
__device__ float g_k[M_*C_];
__device__ float g_v[M_*C_];
__device__ float g_o[M_*C_];

__device__ __forceinline__ uint32_t f2tf32(float x) {
    uint32_t u;
    asm("cvt.rna.tf32.f32 %0, %1;" : "=r"(u) : "f"(x));
    return u;
}

__device__ __forceinline__ void mma_tf32(float c[4],
    uint32_t a0, uint32_t a1, uint32_t a2, uint32_t a3,
    uint32_t b0, uint32_t b1)
{
    asm volatile(
        "mma.sync.aligned.m16n8k8.row.col.f32.tf32.tf32.f32 "
        "{%0,%1,%2,%3},{%4,%5,%6,%7},{%8,%9},{%0,%1,%2,%3};"
        : "+f"(c[0]), "+f"(c[1]), "+f"(c[2]), "+f"(c[3])
        : "r"(a0), "r"(a1), "r"(a2), "r"(a3), "r"(b0), "r"(b1));
}

// ---------------------------------------------------------------------------
// TF32 tensor-core GEMM with bias: C[M,N] = A[M,K] @ W[K,N] + bias[N]
// ---------------------------------------------------------------------------
#define BM 128
#define BN 128
#define BK 32
#define SA 36
#define SB 136

__global__ __launch_bounds__(256) void gemm_tf32_kernel(
    const float* __restrict__ Aext, const float* __restrict__ W,
    const float* __restrict__ bias, float* __restrict__ Oext,
    int asel, int osel, int M, int N, int K)
{
    const float* A = asel ? (const float*)g_o : Aext;
    float* Cm = (osel == 0) ? g_q : (osel == 1) ? g_k : (osel == 2) ? g_v : Oext;

    __shared__ uint32_t As[BM][SA];
    __shared__ uint32_t Ws[BK][SB];

    const int tid  = threadIdx.x;
    const int lane = tid & 31;
    const int warp = tid >> 5;
    const int wr   = warp >> 2;
    const int wc   = warp & 3;
    const int brow = blockIdx.y * BM;
    const int bcol = blockIdx.x * BN;

    const int lg = lane >> 2;
    const int lt = lane & 3;

    float acc[4][4][4];
    #pragma unroll
    for (int mf = 0; mf < 4; mf++)
        #pragma unroll
        for (int nf = 0; nf < 4; nf++)
            #pragma unroll
            for (int r = 0; r < 4; r++) acc[mf][nf][r] = 0.f;

    for (int k0 = 0; k0 < K; k0 += BK) {
        #pragma unroll
        for (int l = 0; l < 4; l++) {
            int f4 = tid + l * 256;
            int r  = f4 >> 3;
            int c4 = (f4 & 7) << 2;
            float4 v = *(const float4*)&A[(size_t)(brow + r) * K + k0 + c4];
            uint4 u = { f2tf32(v.x), f2tf32(v.y), f2tf32(v.z), f2tf32(v.w) };
            *(uint4*)&As[r][c4] = u;
        }
        #pragma unroll
        for (int l = 0; l < 4; l++) {
            int f4 = tid + l * 256;
            int r  = f4 >> 5;
            int c4 = (f4 & 31) << 2;
            float4 v = *(const float4*)&W[(size_t)(k0 + r) * N + bcol + c4];
            uint4 u = { f2tf32(v.x), f2tf32(v.y), f2tf32(v.z), f2tf32(v.w) };
            *(uint4*)&Ws[r][c4] = u;
        }
        __syncthreads();

        #pragma unroll
        for (int ks = 0; ks < 4; ks++) {
            const int kb = ks * 8;
            uint32_t bf[4][2];
            #pragma unroll
            for (int nf = 0; nf < 4; nf++) {
                int n = wc * 32 + nf * 8 + lg;
                bf[nf][0] = Ws[kb + lt][n];
                bf[nf][1] = Ws[kb + 4 + lt][n];
            }
            #pragma unroll
            for (int mf = 0; mf < 4; mf++) {
                int m0 = wr * 64 + mf * 16 + lg;
                uint32_t a0 = As[m0][kb + lt];
                uint32_t a1 = As[m0 + 8][kb + lt];
                uint32_t a2 = As[m0][kb + 4 + lt];
                uint32_t a3 = As[m0 + 8][kb + 4 + lt];
                #pragma unroll
                for (int nf = 0; nf < 4; nf++)
                    mma_tf32(acc[mf][nf], a0, a1, a2, a3, bf[nf][0], bf[nf][1]);
            }
        }
        __syncthreads();
    }

    #pragma unroll
    for (int mf = 0; mf < 4; mf++) {
        int row0 = brow + wr * 64 + mf * 16 + lg;
        #pragma unroll
        for (int nf = 0; nf < 4; nf++) {
            int col = bcol + wc * 32 + nf * 8 + lt * 2;
            float bx = bias[col], by = bias[col + 1];
            float2 o0 = { acc[mf][nf][0] + bx, acc[mf][nf][1] + by };
            float2 o1 = { acc[mf][nf][2] + bx, acc[mf][nf][3] + by };
            *(float2*)&Cm[(size_t)row0 * N + col]       = o0;
            *(float2*)&Cm[(size_t)(row0 + 8) * N + col] = o1;
        }
    }
}

// ---------------------------------------------------------------------------
// Tensor-core flash attention with ALiBi + causal mask (all TF32 mma).
// grid = (T/64, H, B), block = 128 (4 warps). Warp owns 16 query rows.
// SMEM (dynamic): Ks[64][68], Vs[64][72], Ps[4][16][68]  (uint32/tf32 words)
// ---------------------------------------------------------------------------
#define AKT 64
#define SKW 68   // Ks stride: b-frag bank = 4*lg+lt (bijective)
#define SVW 72   // Vs stride: b-frag bank = 8*lt+lg (bijective)
#define SPW 68   // Ps stride: a-frag bank = 4*lg+lt (bijective)
#define KS_OFF 0
#define VS_OFF (AKT*SKW)               // 4352
#define PS_OFF (VS_OFF + AKT*SVW)      // 8960
#define ATT_SMEM ((PS_OFF + 4*16*SPW) * 4)   // 53248 bytes

__global__ __launch_bounds__(128) void attn_mma_kernel()
{
    extern __shared__ uint32_t sm[];
    uint32_t* Ks = sm + KS_OFF;
    uint32_t* Vs = sm + VS_OFF;
    uint32_t* Ps = sm + PS_OFF;

    const int tid  = threadIdx.x;
    const int lane = tid & 31;
    const int warp = tid >> 5;
    const int lg   = lane >> 2;
    const int lt   = lane & 3;
    const int h    = blockIdx.y;
    const int b    = blockIdx.z;
    const int qbase = blockIdx.x * 64;

    const float scale = 0.125f;
    const float slope = exp2f(-0.5f * (float)(h + 1));

    const int r0 = qbase + warp * 16 + lg;
    const int r1 = r0 + 8;

    // Q fragments, scale folded in. qf[ks] = {A[r0][kb+lt], A[r1][kb+lt], A[r0][kb+4+lt], A[r1][kb+4+lt]}
    uint32_t qf[8][4];
    {
        const float* q0 = &g_q[((size_t)(b * T_ + r0)) * C_ + h * D_];
        const float* q1 = &g_q[((size_t)(b * T_ + r1)) * C_ + h * D_];
        #pragma unroll
        for (int ks = 0; ks < 8; ks++) {
            int c = ks * 8 + lt;
            qf[ks][0] = f2tf32(q0[c] * scale);
            qf[ks][1] = f2tf32(q1[c] * scale);
            qf[ks][2] = f2tf32(q0[c + 4] * scale);
            qf[ks][3] = f2tf32(q1[c + 4] * scale);
        }
    }

    float oacc[8][4];
    #pragma unroll
    for (int nf = 0; nf < 8; nf++)
        #pragma unroll
        for (int r = 0; r < 4; r++) oacc[nf][r] = 0.f;
    float m0 = -1e30f, m1 = -1e30f, l0 = 0.f, l1 = 0.f;

    uint32_t* Pw = Ps + warp * 16 * SPW;

    for (int k0 = 0; k0 < qbase + 64; k0 += AKT) {
        __syncthreads();
        // Load K/V tile (64x64 each), tf32-convert. 4 float4 per thread per tensor.
        #pragma unroll
        for (int l = 0; l < 8; l++) {
            int f4 = tid + l * 128;          // 0..1023
            int r  = f4 >> 4;
            int c4 = (f4 & 15) << 2;
            size_t base = ((size_t)(b * T_ + k0 + r)) * C_ + h * D_ + c4;
            float4 kv = *(const float4*)&g_k[base];
            float4 vv = *(const float4*)&g_v[base];
            uint4 ku = { f2tf32(kv.x), f2tf32(kv.y), f2tf32(kv.z), f2tf32(kv.w) };
            uint4 vu = { f2tf32(vv.x), f2tf32(vv.y), f2tf32(vv.z), f2tf32(vv.w) };
            *(uint4*)&Ks[r * SKW + c4] = ku;
            *(uint4*)&Vs[r * SVW + c4] = vu;
        }
        __syncthreads();

        // S = Q K^T  (16x64 per warp)
        float s[8][4];
        #pragma unroll
        for (int nf = 0; nf < 8; nf++)
            #pragma unroll
            for (int r = 0; r < 4; r++) s[nf][r] = 0.f;

        #pragma unroll
        for (int ks = 0; ks < 8; ks++) {
            int kb = ks * 8;
            #pragma unroll
            for (int nf = 0; nf < 8; nf++) {
                int n = nf * 8 + lg;
                uint32_t b0 = Ks[n * SKW + kb + lt];
                uint32_t b1 = Ks[n * SKW + kb + 4 + lt];
                mma_tf32(s[nf], qf[ks][0], qf[ks][1], qf[ks][2], qf[ks][3], b0, b1);
            }
        }

        // ALiBi + causal mask, row max
        float rmax0 = -1e30f, rmax1 = -1e30f;
        #pragma unroll
        for (int nf = 0; nf < 8; nf++) {
            int kj = k0 + nf * 8 + 2 * lt;
            int d00 = kj - r0, d01 = kj + 1 - r0;
            int d10 = kj - r1, d11 = kj + 1 - r1;
            s[nf][0] = (d00 <= 0) ? s[nf][0] + slope * (float)d00 : -1e30f;
            s[nf][1] = (d01 <= 0) ? s[nf][1] + slope * (float)d01 : -1e30f;
            s[nf][2] = (d10 <= 0) ? s[nf][2] + slope * (float)d10 : -1e30f;
            s[nf][3] = (d11 <= 0) ? s[nf][3] + slope * (float)d11 : -1e30f;
            rmax0 = fmaxf(rmax0, fmaxf(s[nf][0], s[nf][1]));
            rmax1 = fmaxf(rmax1, fmaxf(s[nf][2], s[nf][3]));
        }
        rmax0 = fmaxf(rmax0, __shfl_xor_sync(0xffffffffu, rmax0, 1));
        rmax0 = fmaxf(rmax0, __shfl_xor_sync(0xffffffffu, rmax0, 2));
        rmax1 = fmaxf(rmax1, __shfl_xor_sync(0xffffffffu, rmax1, 1));
        rmax1 = fmaxf(rmax1, __shfl_xor_sync(0xffffffffu, rmax1, 2));

        float mn0 = fmaxf(m0, rmax0), mn1 = fmaxf(m1, rmax1);
        float c0 = __expf(m0 - mn0),  c1 = __expf(m1 - mn1);
        l0 *= c0; l1 *= c1;
        m0 = mn0; m1 = mn1;

        // P = exp(S - m), store to SMEM (tf32), accumulate row sums
        float rs0 = 0.f, rs1 = 0.f;
        #pragma unroll
        for (int nf = 0; nf < 8; nf++) {
            float p00 = __expf(s[nf][0] - mn0);
            float p01 = __expf(s[nf][1] - mn0);
            float p10 = __expf(s[nf][2] - mn1);
            float p11 = __expf(s[nf][3] - mn1);
            rs0 += p00 + p01;
            rs1 += p10 + p11;
            uint32_t* pr = &Pw[lg * SPW + nf * 8 + 2 * lt];
            uint2 u0 = { f2tf32(p00), f2tf32(p01) };
            uint2 u1 = { f2tf32(p10), f2tf32(p11) };
            *(uint2*)pr = u0;
            *(uint2*)(pr + 8 * SPW) = u1;
        }
        rs0 += __shfl_xor_sync(0xffffffffu, rs0, 1);
        rs0 += __shfl_xor_sync(0xffffffffu, rs0, 2);
        rs1 += __shfl_xor_sync(0xffffffffu, rs1, 1);
        rs1 += __shfl_xor_sync(0xffffffffu, rs1, 2);
        l0 += rs0; l1 += rs1;

        // Rescale O accumulators
        #pragma unroll
        for (int nf = 0; nf < 8; nf++) {
            oacc[nf][0] *= c0; oacc[nf][1] *= c0;
            oacc[nf][2] *= c1; oacc[nf][3] *= c1;
        }

        __syncwarp();

        // O += P V   (P: 16x64 keys, V: 64 keys x 64 dims)
        #pragma unroll
        for (int ks = 0; ks < 8; ks++) {
            int kb = ks * 8;
            uint32_t a0 = Pw[lg * SPW + kb + lt];
            uint32_t a1 = Pw[(lg + 8) * SPW + kb + lt];
            uint32_t a2 = Pw[lg * SPW + kb + 4 + lt];
            uint32_t a3 = Pw[(lg + 8) * SPW + kb + 4 + lt];
            #pragma unroll
            for (int nf = 0; nf < 8; nf++) {
                int n = nf * 8 + lg;
                uint32_t b0 = Vs[(kb + lt) * SVW + n];
                uint32_t b1 = Vs[(kb + 4 + lt) * SVW + n];
                mma_tf32(oacc[nf], a0, a1, a2, a3, b0, b1);
            }
        }
    }

    // Final normalize + store
    float inv0 = 1.f / l0, inv1 = 1.f / l1;
    float* o0 = &g_o[((size_t)(b * T_ + r0)) * C_ + h * D_];
    float* o1 = &g_o[((size_t)(b * T_ + r1)) * C_ + h * D_];
    #pragma unroll
    for (int nf = 0; nf < 8; nf++) {
        int c = nf * 8 + 2 * lt;
        float2 v0 = { oacc[nf][0] * inv0, oacc[nf][1] * inv0 };
        float2 v1 = { oacc[nf][2] * inv1, oacc[nf][3] * inv1 };
        *(float2*)&o0[c] = v0;
        *(float2*)&o1[c] = v1;
    }
}

// ---------------------------------------------------------------------------
extern "C" void kernel_launch(void* const* d_in, const int* in_sizes, int n_in,
                              void* d_out, int out_size)
{
    const float* x  = (const float*)d_in[0];
    const float* Wq = (const float*)d_in[1];
    const float* bq = (const float*)d_in[2];
    const float* Wk = (const float*)d_in[3];
    const float* bk = (const float*)d_in[4];
    const float* Wv = (const float*)d_in[5];
    const float* bv = (const float*)d_in[6];
    const float* Wo = (const float*)d_in[7];
    const float* bo = (const float*)d_in[8];
    float* out = (float*)d_out;

    cudaFuncSetAttribute(attn_mma_kernel,
                         cudaFuncAttributeMaxDynamicSharedMemorySize, ATT_SMEM);

    dim3 gp(C_ / BN, M_ / BM);   // (8, 32)

    gemm_tf32_kernel<<<gp, 256>>>(x, Wq, bq, nullptr, 0, 0, M_, C_, C_);
    gemm_tf32_kernel<<<gp, 256>>>(x, Wk, bk, nullptr, 0, 1, M_, C_, C_);
    gemm_tf32_kernel<<<gp, 256>>>(x, Wv, bv, nullptr, 0, 2, M_, C_, C_);

    attn_mma_kernel<<<dim3(T_ / 64, H_, B_), 128, ATT_SMEM>>>();

    gemm_tf32_kernel<<<gp, 256>>>(nullptr, Wo, bo, out, 1, 3, M_, C_, C_);
}

// round 4
// speedup vs baseline: 4.1767x; 1.0481x over previous
#include <cuda_runtime.h>
#include <stdint.h>
#include <math.h>

#define B_ 2
#define T_ 2048
#define C_ 1024
#define H_ 16
#define D_ 64
#define M_ (B_*T_)   // 4096 rows

// Scratch (allocation-free): Q, K, V, attention-out, each 16 MB fp32.
__device__ float g_q[M_*C_];
__device__ float g_k[M_*C_];
__device__ float g_v[M_*C_];
__device__ float g_o[M_*C_];

__device__ __forceinline__ uint32_t f2tf32(float x) {
    uint32_t u;
    asm("cvt.rna.tf32.f32 %0, %1;" : "=r"(u) : "f"(x));
    return u;
}

__device__ __forceinline__ float ex2f(float x) {
    float y;
    asm("ex2.approx.ftz.f32 %0, %1;" : "=f"(y) : "f"(x));
    return y;
}

__device__ __forceinline__ void mma_tf32(float c[4],
    uint32_t a0, uint32_t a1, uint32_t a2, uint32_t a3,
    uint32_t b0, uint32_t b1)
{
    asm volatile(
        "mma.sync.aligned.m16n8k8.row.col.f32.tf32.tf32.f32 "
        "{%0,%1,%2,%3},{%4,%5,%6,%7},{%8,%9},{%0,%1,%2,%3};"
        : "+f"(c[0]), "+f"(c[1]), "+f"(c[2]), "+f"(c[3])
        : "r"(a0), "r"(a1), "r"(a2), "r"(a3), "r"(b0), "r"(b1));
}

// ---------------------------------------------------------------------------
// Pipelined TF32 GEMM body: C[M,N] = A[M,K] @ W[K,N] + bias[N]
// 128x128 tile, BK=32, 256 thr (8 warps 2x4), warp 64x32, 2-stage SMEM,
// register double-buffered global loads, one __syncthreads per k-iter.
// ---------------------------------------------------------------------------
#define BM 128
#define BN 128
#define BK 32
#define SA 36
#define SB 136
#define STG_W (BM*SA + BK*SB)     // 8960 words per stage
#define GEMM_SMEM (2*STG_W*4)     // 71680 bytes

__device__ __forceinline__ void gemm_load_tiles(
    const float* A, const float* W, int N, int K, int brow, int bcol, int k0,
    int tid, float4* ra, float4* rw)
{
    #pragma unroll
    for (int l = 0; l < 4; l++) {
        int f4 = tid + (l << 8);
        ra[l] = *(const float4*)&A[(size_t)(brow + (f4 >> 3)) * K + k0 + ((f4 & 7) << 2)];
        rw[l] = *(const float4*)&W[(size_t)(k0 + (f4 >> 5)) * N + bcol + ((f4 & 31) << 2)];
    }
}

__device__ __forceinline__ void gemm_store_stage(
    uint32_t* st, const float4* ra, const float4* rw, int tid)
{
    uint32_t* As = st;
    uint32_t* Ws = st + BM * SA;
    #pragma unroll
    for (int l = 0; l < 4; l++) {
        int f4 = tid + (l << 8);
        int ar = f4 >> 3, ac = (f4 & 7) << 2;
        uint4 ua = { f2tf32(ra[l].x), f2tf32(ra[l].y), f2tf32(ra[l].z), f2tf32(ra[l].w) };
        *(uint4*)&As[ar * SA + ac] = ua;
        int wr_ = f4 >> 5, wc_ = (f4 & 31) << 2;
        uint4 uw = { f2tf32(rw[l].x), f2tf32(rw[l].y), f2tf32(rw[l].z), f2tf32(rw[l].w) };
        *(uint4*)&Ws[wr_ * SB + wc_] = uw;
    }
}

__device__ __forceinline__ void gemm_pipe(
    const float* __restrict__ A, const float* __restrict__ W,
    const float* __restrict__ bias, float* __restrict__ Cm,
    int N, int K, int brow, int bcol)
{
    extern __shared__ uint32_t smem[];
    const int tid  = threadIdx.x;
    const int lane = tid & 31;
    const int warp = tid >> 5;
    const int wr   = warp >> 2;
    const int wc   = warp & 3;
    const int lg   = lane >> 2;
    const int lt   = lane & 3;

    float acc[4][4][4];
    #pragma unroll
    for (int mf = 0; mf < 4; mf++)
        #pragma unroll
        for (int nf = 0; nf < 4; nf++)
            #pragma unroll
            for (int r = 0; r < 4; r++) acc[mf][nf][r] = 0.f;

    float4 ra[4], rw[4];
    gemm_load_tiles(A, W, N, K, brow, bcol, 0, tid, ra, rw);
    gemm_store_stage(smem, ra, rw, tid);
    __syncthreads();

    int cur = 0;
    for (int k0 = 0; k0 < K; k0 += BK) {
        int kn = k0 + BK;
        if (kn < K) gemm_load_tiles(A, W, N, K, brow, bcol, kn, tid, ra, rw);

        const uint32_t* As = smem + cur * STG_W;
        const uint32_t* Ws = As + BM * SA;
        #pragma unroll
        for (int ks = 0; ks < 4; ks++) {
            const int kb = ks * 8;
            uint32_t bf[4][2];
            #pragma unroll
            for (int nf = 0; nf < 4; nf++) {
                int n = wc * 32 + nf * 8 + lg;
                bf[nf][0] = Ws[(kb + lt) * SB + n];
                bf[nf][1] = Ws[(kb + 4 + lt) * SB + n];
            }
            #pragma unroll
            for (int mf = 0; mf < 4; mf++) {
                int m0 = wr * 64 + mf * 16 + lg;
                uint32_t a0 = As[m0 * SA + kb + lt];
                uint32_t a1 = As[(m0 + 8) * SA + kb + lt];
                uint32_t a2 = As[m0 * SA + kb + 4 + lt];
                uint32_t a3 = As[(m0 + 8) * SA + kb + 4 + lt];
                #pragma unroll
                for (int nf = 0; nf < 4; nf++)
                    mma_tf32(acc[mf][nf], a0, a1, a2, a3, bf[nf][0], bf[nf][1]);
            }
        }

        if (kn < K) {
            gemm_store_stage(smem + (cur ^ 1) * STG_W, ra, rw, tid);
            __syncthreads();
            cur ^= 1;
        }
    }

    #pragma unroll
    for (int mf = 0; mf < 4; mf++) {
        int row0 = brow + wr * 64 + mf * 16 + lg;
        #pragma unroll
        for (int nf = 0; nf < 4; nf++) {
            int col = bcol + wc * 32 + nf * 8 + lt * 2;
            float bx = bias[col], by = bias[col + 1];
            float2 o0 = { acc[mf][nf][0] + bx, acc[mf][nf][1] + by };
            float2 o1 = { acc[mf][nf][2] + bx, acc[mf][nf][3] + by };
            *(float2*)&Cm[(size_t)row0 * N + col]       = o0;
            *(float2*)&Cm[(size_t)(row0 + 8) * N + col] = o1;
        }
    }
}

// Fused QKV projection: grid (24, 32). x-block [0..7]->Q, [8..15]->K, [16..23]->V.
__global__ __launch_bounds__(256) void qkv_gemm_kernel(
    const float* __restrict__ x,
    const float* __restrict__ Wq, const float* __restrict__ bq,
    const float* __restrict__ Wk, const float* __restrict__ bk,
    const float* __restrict__ Wv, const float* __restrict__ bv)
{
    int sel  = blockIdx.x >> 3;
    int bcol = (blockIdx.x & 7) * BN;
    int brow = blockIdx.y * BM;
    const float* W    = (sel == 0) ? Wq : (sel == 1) ? Wk : Wv;
    const float* bias = (sel == 0) ? bq : (sel == 1) ? bk : bv;
    float* Cm         = (sel == 0) ? g_q : (sel == 1) ? g_k : g_v;
    gemm_pipe(x, W, bias, Cm, C_, C_, brow, bcol);
}

__global__ __launch_bounds__(256) void out_gemm_kernel(
    const float* __restrict__ Wo, const float* __restrict__ bo,
    float* __restrict__ out)
{
    gemm_pipe(g_o, Wo, bo, out, C_, C_, blockIdx.y * BM, blockIdx.x * BN);
}

// ---------------------------------------------------------------------------
// Tensor-core flash attention with ALiBi + causal mask (TF32 mma).
// grid = (T/64, H, B), block = 128 (4 warps). Warp owns 16 query rows.
// Scores kept in log2 domain (log2e folded into scale & slope) -> raw EX2.
// ---------------------------------------------------------------------------
#define AKT 64
#define SKW 68
#define SVW 72
#define SPW 68
#define KS_OFF 0
#define VS_OFF (AKT*SKW)
#define PS_OFF (VS_OFF + AKT*SVW)
#define ATT_SMEM ((PS_OFF + 4*16*SPW) * 4)   // 53248 bytes

__global__ __launch_bounds__(128) void attn_mma_kernel()
{
    extern __shared__ uint32_t sm[];
    uint32_t* Ks = sm + KS_OFF;
    uint32_t* Vs = sm + VS_OFF;
    uint32_t* Ps = sm + PS_OFF;

    const int tid  = threadIdx.x;
    const int lane = tid & 31;
    const int warp = tid >> 5;
    const int lg   = lane >> 2;
    const int lt   = lane & 3;
    const int h    = blockIdx.y;
    const int b    = blockIdx.z;
    const int qbase = blockIdx.x * 64;

    const float LOG2E = 1.4426950408889634f;
    const float scale = 0.125f * LOG2E;                          // fold log2e
    const float slope = exp2f(-0.5f * (float)(h + 1)) * LOG2E;   // fold log2e

    const int r0 = qbase + warp * 16 + lg;
    const int r1 = r0 + 8;
    const int wmin = qbase + warp * 16;   // min row of this warp

    uint32_t qf[8][4];
    {
        const float* q0 = &g_q[((size_t)(b * T_ + r0)) * C_ + h * D_];
        const float* q1 = &g_q[((size_t)(b * T_ + r1)) * C_ + h * D_];
        #pragma unroll
        for (int ks = 0; ks < 8; ks++) {
            int c = ks * 8 + lt;
            qf[ks][0] = f2tf32(q0[c] * scale);
            qf[ks][1] = f2tf32(q1[c] * scale);
            qf[ks][2] = f2tf32(q0[c + 4] * scale);
            qf[ks][3] = f2tf32(q1[c + 4] * scale);
        }
    }

    float oacc[8][4];
    #pragma unroll
    for (int nf = 0; nf < 8; nf++)
        #pragma unroll
        for (int r = 0; r < 4; r++) oacc[nf][r] = 0.f;
    float m0 = -1e30f, m1 = -1e30f, l0 = 0.f, l1 = 0.f;

    uint32_t* Pw = Ps + warp * 16 * SPW;

    for (int k0 = 0; k0 < qbase + 64; k0 += AKT) {
        __syncthreads();
        #pragma unroll
        for (int l = 0; l < 8; l++) {
            int f4 = tid + l * 128;
            int r  = f4 >> 4;
            int c4 = (f4 & 15) << 2;
            size_t base = ((size_t)(b * T_ + k0 + r)) * C_ + h * D_ + c4;
            float4 kv = *(const float4*)&g_k[base];
            float4 vv = *(const float4*)&g_v[base];
            uint4 ku = { f2tf32(kv.x), f2tf32(kv.y), f2tf32(kv.z), f2tf32(kv.w) };
            uint4 vu = { f2tf32(vv.x), f2tf32(vv.y), f2tf32(vv.z), f2tf32(vv.w) };
            *(uint4*)&Ks[r * SKW + c4] = ku;
            *(uint4*)&Vs[r * SVW + c4] = vu;
        }
        __syncthreads();

        // S = Q K^T
        float s[8][4];
        #pragma unroll
        for (int nf = 0; nf < 8; nf++)
            #pragma unroll
            for (int r = 0; r < 4; r++) s[nf][r] = 0.f;

        #pragma unroll
        for (int ks = 0; ks < 8; ks++) {
            int kb = ks * 8;
            #pragma unroll
            for (int nf = 0; nf < 8; nf++) {
                int n = nf * 8 + lg;
                uint32_t b0 = Ks[n * SKW + kb + lt];
                uint32_t b1 = Ks[n * SKW + kb + 4 + lt];
                mma_tf32(s[nf], qf[ks][0], qf[ks][1], qf[ks][2], qf[ks][3], b0, b1);
            }
        }

        // ALiBi + causal mask + row max. Interior tiles need no mask.
        float rmax0 = -1e30f, rmax1 = -1e30f;
        if (k0 + AKT - 1 <= wmin) {
            #pragma unroll
            for (int nf = 0; nf < 8; nf++) {
                int kj = k0 + nf * 8 + 2 * lt;
                s[nf][0] += slope * (float)(kj - r0);
                s[nf][1] += slope * (float)(kj + 1 - r0);
                s[nf][2] += slope * (float)(kj - r1);
                s[nf][3] += slope * (float)(kj + 1 - r1);
                rmax0 = fmaxf(rmax0, fmaxf(s[nf][0], s[nf][1]));
                rmax1 = fmaxf(rmax1, fmaxf(s[nf][2], s[nf][3]));
            }
        } else {
            #pragma unroll
            for (int nf = 0; nf < 8; nf++) {
                int kj = k0 + nf * 8 + 2 * lt;
                int d00 = kj - r0, d01 = kj + 1 - r0;
                int d10 = kj - r1, d11 = kj + 1 - r1;
                s[nf][0] = (d00 <= 0) ? s[nf][0] + slope * (float)d00 : -1e30f;
                s[nf][1] = (d01 <= 0) ? s[nf][1] + slope * (float)d01 : -1e30f;
                s[nf][2] = (d10 <= 0) ? s[nf][2] + slope * (float)d10 : -1e30f;
                s[nf][3] = (d11 <= 0) ? s[nf][3] + slope * (float)d11 : -1e30f;
                rmax0 = fmaxf(rmax0, fmaxf(s[nf][0], s[nf][1]));
                rmax1 = fmaxf(rmax1, fmaxf(s[nf][2], s[nf][3]));
            }
        }
        rmax0 = fmaxf(rmax0, __shfl_xor_sync(0xffffffffu, rmax0, 1));
        rmax0 = fmaxf(rmax0, __shfl_xor_sync(0xffffffffu, rmax0, 2));
        rmax1 = fmaxf(rmax1, __shfl_xor_sync(0xffffffffu, rmax1, 1));
        rmax1 = fmaxf(rmax1, __shfl_xor_sync(0xffffffffu, rmax1, 2));

        float mn0 = fmaxf(m0, rmax0), mn1 = fmaxf(m1, rmax1);
        float c0 = ex2f(m0 - mn0),  c1 = ex2f(m1 - mn1);
        l0 *= c0; l1 *= c1;
        m0 = mn0; m1 = mn1;

        float rs0 = 0.f, rs1 = 0.f;
        #pragma unroll
        for (int nf = 0; nf < 8; nf++) {
            float p00 = ex2f(s[nf][0] - mn0);
            float p01 = ex2f(s[nf][1] - mn0);
            float p10 = ex2f(s[nf][2] - mn1);
            float p11 = ex2f(s[nf][3] - mn1);
            rs0 += p00 + p01;
            rs1 += p10 + p11;
            uint32_t* pr = &Pw[lg * SPW + nf * 8 + 2 * lt];
            uint2 u0 = { f2tf32(p00), f2tf32(p01) };
            uint2 u1 = { f2tf32(p10), f2tf32(p11) };
            *(uint2*)pr = u0;
            *(uint2*)(pr + 8 * SPW) = u1;
        }
        rs0 += __shfl_xor_sync(0xffffffffu, rs0, 1);
        rs0 += __shfl_xor_sync(0xffffffffu, rs0, 2);
        rs1 += __shfl_xor_sync(0xffffffffu, rs1, 1);
        rs1 += __shfl_xor_sync(0xffffffffu, rs1, 2);
        l0 += rs0; l1 += rs1;

        #pragma unroll
        for (int nf = 0; nf < 8; nf++) {
            oacc[nf][0] *= c0; oacc[nf][1] *= c0;
            oacc[nf][2] *= c1; oacc[nf][3] *= c1;
        }

        __syncwarp();

        #pragma unroll
        for (int ks = 0; ks < 8; ks++) {
            int kb = ks * 8;
            uint32_t a0 = Pw[lg * SPW + kb + lt];
            uint32_t a1 = Pw[(lg + 8) * SPW + kb + lt];
            uint32_t a2 = Pw[lg * SPW + kb + 4 + lt];
            uint32_t a3 = Pw[(lg + 8) * SPW + kb + 4 + lt];
            #pragma unroll
            for (int nf = 0; nf < 8; nf++) {
                int n = nf * 8 + lg;
                uint32_t b0 = Vs[(kb + lt) * SVW + n];
                uint32_t b1 = Vs[(kb + 4 + lt) * SVW + n];
                mma_tf32(oacc[nf], a0, a1, a2, a3, b0, b1);
            }
        }
    }

    float inv0 = 1.f / l0, inv1 = 1.f / l1;
    float* o0 = &g_o[((size_t)(b * T_ + r0)) * C_ + h * D_];
    float* o1 = &g_o[((size_t)(b * T_ + r1)) * C_ + h * D_];
    #pragma unroll
    for (int nf = 0; nf < 8; nf++) {
        int c = nf * 8 + 2 * lt;
        float2 v0 = { oacc[nf][0] * inv0, oacc[nf][1] * inv0 };
        float2 v1 = { oacc[nf][2] * inv1, oacc[nf][3] * inv1 };
        *(float2*)&o0[c] = v0;
        *(float2*)&o1[c] = v1;
    }
}

// ---------------------------------------------------------------------------
extern "C" void kernel_launch(void* const* d_in, const int* in_sizes, int n_in,
                              void* d_out, int out_size)
{
    const float* x  = (const float*)d_in[0];
    const float* Wq = (const float*)d_in[1];
    const float* bq = (const float*)d_in[2];
    const float* Wk = (const float*)d_in[3];
    const float* bk = (const float*)d_in[4];
    const float* Wv = (const float*)d_in[5];
    const float* bv = (const float*)d_in[6];
    const float* Wo = (const float*)d_in[7];
    const float* bo = (const float*)d_in[8];
    float* out = (float*)d_out;

    cudaFuncSetAttribute(qkv_gemm_kernel,
                         cudaFuncAttributeMaxDynamicSharedMemorySize, GEMM_SMEM);
    cudaFuncSetAttribute(out_gemm_kernel,
                         cudaFuncAttributeMaxDynamicSharedMemorySize, GEMM_SMEM);
    cudaFuncSetAttribute(attn_mma_kernel,
                         cudaFuncAttributeMaxDynamicSharedMemorySize, ATT_SMEM);

    qkv_gemm_kernel<<<dim3(24, 32), 256, GEMM_SMEM>>>(x, Wq, bq, Wk, bk, Wv, bv);

    attn_mma_kernel<<<dim3(T_ / 64, H_, B_), 128, ATT_SMEM>>>();

    out_gemm_kernel<<<dim3(8, 32), 256, GEMM_SMEM>>>(Wo, bo, out);
}

// round 6
// speedup vs baseline: 4.4837x; 1.0735x over previous
#include <cuda_runtime.h>
#include <stdint.h>
#include <math.h>

#define B_ 2
#define T_ 2048
#define C_ 1024
#define H_ 16
#define D_ 64
#define M_ (B_*T_)   // 4096 rows

// Scratch (allocation-free).
__device__ float g_q[M_*C_];
__device__ float g_k[M_*C_];
__device__ float g_v[M_*C_];
__device__ float g_o[M_*C_];
__device__ float g_xt[M_*C_];      // tf32-rounded x
__device__ float g_wt[4*C_*C_];    // tf32-rounded Wq,Wk,Wv,Wo

__device__ __forceinline__ uint32_t f2tf32(float x) {
    uint32_t u;
    asm("cvt.rna.tf32.f32 %0, %1;" : "=r"(u) : "f"(x));
    return u;
}

__device__ __forceinline__ float ex2f(float x) {
    float y;
    asm("ex2.approx.ftz.f32 %0, %1;" : "=f"(y) : "f"(x));
    return y;
}

__device__ __forceinline__ void mma_tf32(float c[4],
    uint32_t a0, uint32_t a1, uint32_t a2, uint32_t a3,
    uint32_t b0, uint32_t b1)
{
    asm volatile(
        "mma.sync.aligned.m16n8k8.row.col.f32.tf32.tf32.f32 "
        "{%0,%1,%2,%3},{%4,%5,%6,%7},{%8,%9},{%0,%1,%2,%3};"
        : "+f"(c[0]), "+f"(c[1]), "+f"(c[2]), "+f"(c[3])
        : "r"(a0), "r"(a1), "r"(a2), "r"(a3), "r"(b0), "r"(b1));
}

__device__ __forceinline__ void cpa16(void* dst, const void* src) {
    uint32_t d = (uint32_t)__cvta_generic_to_shared(dst);
    asm volatile("cp.async.cg.shared.global [%0], [%1], 16;" :: "r"(d), "l"(src));
}
#define CP_COMMIT() asm volatile("cp.async.commit_group;")
#define CP_WAIT(N)  asm volatile("cp.async.wait_group %0;" :: "n"(N))

// ---------------------------------------------------------------------------
// Pre-round x and the 4 weight matrices to tf32 (rna) once.
// ---------------------------------------------------------------------------
__global__ __launch_bounds__(256) void conv_kernel(
    const float* __restrict__ x,  const float* __restrict__ Wq,
    const float* __restrict__ Wk, const float* __restrict__ Wv,
    const float* __restrict__ Wo)
{
    const float* Ws[4] = { Wq, Wk, Wv, Wo };
    int base = blockIdx.x * 256 + threadIdx.x;
    #pragma unroll
    for (int l = 0; l < 4; l++) {
        int i4 = base + l * (2048 * 256);
        int r  = i4 >> 18;
        const float* src;
        float* dst;
        if (r < 4) { src = x + ((size_t)i4 << 2); dst = g_xt + ((size_t)i4 << 2); }
        else {
            int off = i4 & 0x3FFFF;
            src = Ws[r - 4] + ((size_t)off << 2);
            dst = g_wt + ((size_t)(r - 4) << 20) + ((size_t)off << 2);
        }
        float4 v = *(const float4*)src;
        uint4 u = { f2tf32(v.x), f2tf32(v.y), f2tf32(v.z), f2tf32(v.w) };
        *(uint4*)dst = u;
    }
}

// ---------------------------------------------------------------------------
// 3-stage cp.async TF32 GEMM: C = A @ W + bias. A,W pre-rounded tf32.
// 128x128 tile, BK=32, 256 thr (8 warps 2x4), warp 64x32.
// ---------------------------------------------------------------------------
#define BM 128
#define BN 128
#define BK 32
#define SA 36
#define SB 136
#define STG_W (BM*SA + BK*SB)       // 8960 words
#define GEMM_SMEM (3*STG_W*4)       // 107520 bytes

__device__ __forceinline__ void gemm_issue(
    uint32_t* stage, const float* A, const float* W,
    int brow, int bcol, int k0, int tid)
{
    uint32_t* As = stage;
    uint32_t* Ws = stage + BM * SA;
    #pragma unroll
    for (int l = 0; l < 4; l++) {          // 4*256 = 1024 float4 per tensor
        int f4 = tid + (l << 8);
        int ar = f4 >> 3, ac = (f4 & 7) << 2;
        cpa16(&As[ar * SA + ac], &A[(size_t)(brow + ar) * C_ + k0 + ac]);
        int wr_ = f4 >> 5, wc_ = (f4 & 31) << 2;
        cpa16(&Ws[wr_ * SB + wc_], &W[(size_t)(k0 + wr_) * C_ + bcol + wc_]);
    }
}

__device__ __forceinline__ void gemm_pipe(
    const float* __restrict__ A, const float* __restrict__ W,
    const float* __restrict__ bias, float* __restrict__ Cm,
    int brow, int bcol, int roundOut)
{
    extern __shared__ uint32_t smem[];
    const int tid  = threadIdx.x;
    const int lane = tid & 31;
    const int warp = tid >> 5;
    const int wr   = warp >> 2;
    const int wc   = warp & 3;
    const int lg   = lane >> 2;
    const int lt   = lane & 3;

    float acc[4][4][4];
    #pragma unroll
    for (int mf = 0; mf < 4; mf++)
        #pragma unroll
        for (int nf = 0; nf < 4; nf++)
            #pragma unroll
            for (int r = 0; r < 4; r++) acc[mf][nf][r] = 0.f;

    gemm_issue(smem,         A, W, brow, bcol, 0,  tid); CP_COMMIT();
    gemm_issue(smem + STG_W, A, W, brow, bcol, BK, tid); CP_COMMIT();

    const int NIT = C_ / BK;   // 32
    #pragma unroll 1
    for (int it = 0; it < NIT; it++) {
        CP_WAIT(1);
        __syncthreads();
        int kn = (it + 2) * BK;
        if (kn < C_) gemm_issue(smem + ((it + 2) % 3) * STG_W, A, W, brow, bcol, kn, tid);
        CP_COMMIT();

        const uint32_t* As = smem + (it % 3) * STG_W;
        const uint32_t* Ws = As + BM * SA;
        #pragma unroll
        for (int ks = 0; ks < 4; ks++) {
            const int kb = ks * 8;
            uint32_t bf[4][2];
            #pragma unroll
            for (int nf = 0; nf < 4; nf++) {
                int n = wc * 32 + nf * 8 + lg;
                bf[nf][0] = Ws[(kb + lt) * SB + n];
                bf[nf][1] = Ws[(kb + 4 + lt) * SB + n];
            }
            #pragma unroll
            for (int mf = 0; mf < 4; mf++) {
                int m0 = wr * 64 + mf * 16 + lg;
                uint32_t a0 = As[m0 * SA + kb + lt];
                uint32_t a1 = As[(m0 + 8) * SA + kb + lt];
                uint32_t a2 = As[m0 * SA + kb + 4 + lt];
                uint32_t a3 = As[(m0 + 8) * SA + kb + 4 + lt];
                #pragma unroll
                for (int nf = 0; nf < 4; nf++)
                    mma_tf32(acc[mf][nf], a0, a1, a2, a3, bf[nf][0], bf[nf][1]);
            }
        }
    }

    #pragma unroll
    for (int mf = 0; mf < 4; mf++) {
        int row0 = brow + wr * 64 + mf * 16 + lg;
        #pragma unroll
        for (int nf = 0; nf < 4; nf++) {
            int col = bcol + wc * 32 + nf * 8 + lt * 2;
            float bx = bias[col], by = bias[col + 1];
            float v00 = acc[mf][nf][0] + bx, v01 = acc[mf][nf][1] + by;
            float v10 = acc[mf][nf][2] + bx, v11 = acc[mf][nf][3] + by;
            if (roundOut) {
                uint2 o0 = { f2tf32(v00), f2tf32(v01) };
                uint2 o1 = { f2tf32(v10), f2tf32(v11) };
                *(uint2*)&Cm[(size_t)row0 * C_ + col]       = o0;
                *(uint2*)&Cm[(size_t)(row0 + 8) * C_ + col] = o1;
            } else {
                float2 o0 = { v00, v01 };
                float2 o1 = { v10, v11 };
                *(float2*)&Cm[(size_t)row0 * C_ + col]       = o0;
                *(float2*)&Cm[(size_t)(row0 + 8) * C_ + col] = o1;
            }
        }
    }
}

// Fused QKV projection: grid (24, 32).
__global__ __launch_bounds__(256) void qkv_gemm_kernel(
    const float* __restrict__ bq, const float* __restrict__ bk,
    const float* __restrict__ bv)
{
    int sel  = blockIdx.x >> 3;
    int bcol = (blockIdx.x & 7) * BN;
    int brow = blockIdx.y * BM;
    const float* W    = g_wt + ((size_t)sel << 20);
    const float* bias = (sel == 0) ? bq : (sel == 1) ? bk : bv;
    float* Cm         = (sel == 0) ? g_q : (sel == 1) ? g_k : g_v;
    gemm_pipe(g_xt, W, bias, Cm, brow, bcol, 1);
}

__global__ __launch_bounds__(256) void out_gemm_kernel(
    const float* __restrict__ bo, float* __restrict__ out)
{
    gemm_pipe(g_o, g_wt + ((size_t)3 << 20), bo, out,
              blockIdx.y * BM, blockIdx.x * BN, 0);
}

// ---------------------------------------------------------------------------
// TF32 flash attention, ALiBi + causal, cp.async double-buffered K/V,
// P overlays current Ks buffer. grid (T/64, H, B), 128 thr (4 warps).
// ---------------------------------------------------------------------------
#define AKT 64
#define SKW 68
#define SVW 72
#define AST_W (AKT*SKW + AKT*SVW)          // 8960 words per stage
#define ATT_SMEM (2*AST_W*4)               // 71680 bytes

__device__ __forceinline__ void attn_issue_kv(
    uint32_t* stage, int b, int h, int k0, int tid)
{
    uint32_t* Ks = stage;
    uint32_t* Vs = stage + AKT * SKW;
    #pragma unroll
    for (int l = 0; l < 8; l++) {
        int f4 = tid + l * 128;
        int r  = f4 >> 4;
        int c4 = (f4 & 15) << 2;
        size_t base = ((size_t)(b * T_ + k0 + r)) * C_ + h * D_ + c4;
        cpa16(&Ks[r * SKW + c4], &g_k[base]);
        cpa16(&Vs[r * SVW + c4], &g_v[base]);
    }
}

__global__ __launch_bounds__(128) void attn_mma_kernel()
{
    extern __shared__ uint32_t sm[];

    const int tid  = threadIdx.x;
    const int lane = tid & 31;
    const int warp = tid >> 5;
    const int lg   = lane >> 2;
    const int lt   = lane & 3;
    const int h    = blockIdx.y;
    const int b    = blockIdx.z;
    const int qbase = blockIdx.x * 64;

    const float LOG2E = 1.4426950408889634f;
    const float scale = 0.125f * LOG2E;
    const float slope = exp2f(-0.5f * (float)(h + 1)) * LOG2E;

    const int r0 = qbase + warp * 16 + lg;
    const int r1 = r0 + 8;
    const int wmin = qbase + warp * 16;

    uint32_t qf[8][4];
    {
        const float* q0 = &g_q[((size_t)(b * T_ + r0)) * C_ + h * D_];
        const float* q1 = &g_q[((size_t)(b * T_ + r1)) * C_ + h * D_];
        #pragma unroll
        for (int ks = 0; ks < 8; ks++) {
            int c = ks * 8 + lt;
            qf[ks][0] = f2tf32(q0[c] * scale);
            qf[ks][1] = f2tf32(q1[c] * scale);
            qf[ks][2] = f2tf32(q0[c + 4] * scale);
            qf[ks][3] = f2tf32(q1[c + 4] * scale);
        }
    }

    float oacc[8][4];
    #pragma unroll
    for (int nf = 0; nf < 8; nf++)
        #pragma unroll
        for (int r = 0; r < 4; r++) oacc[nf][r] = 0.f;
    float m0 = -1e30f, m1 = -1e30f, l0 = 0.f, l1 = 0.f;

    const int ntiles = blockIdx.x + 1;

    attn_issue_kv(sm, b, h, 0, tid); CP_COMMIT();

    #pragma unroll 1
    for (int t = 0; t < ntiles; t++) {
        CP_WAIT(0);
        __syncthreads();
        if (t + 1 < ntiles)
            attn_issue_kv(sm + ((t + 1) & 1) * AST_W, b, h, (t + 1) * AKT, tid);
        CP_COMMIT();

        uint32_t* Ks = sm + (t & 1) * AST_W;
        uint32_t* Vs = Ks + AKT * SKW;
        uint32_t* Pw = Ks + warp * 16 * SKW;   // P overlays current Ks
        const int k0 = t * AKT;

        // S = Q K^T
        float s[8][4];
        #pragma unroll
        for (int nf = 0; nf < 8; nf++)
            #pragma unroll
            for (int r = 0; r < 4; r++) s[nf][r] = 0.f;

        #pragma unroll
        for (int ks = 0; ks < 8; ks++) {
            int kb = ks * 8;
            #pragma unroll
            for (int nf = 0; nf < 8; nf++) {
                int n = nf * 8 + lg;
                uint32_t b0 = Ks[n * SKW + kb + lt];
                uint32_t b1 = Ks[n * SKW + kb + 4 + lt];
                mma_tf32(s[nf], qf[ks][0], qf[ks][1], qf[ks][2], qf[ks][3], b0, b1);
            }
        }

        // ALiBi + causal + row max (interior tiles skip the mask)
        float rmax0 = -1e30f, rmax1 = -1e30f;
        if (k0 + AKT - 1 <= wmin) {
            #pragma unroll
            for (int nf = 0; nf < 8; nf++) {
                int kj = k0 + nf * 8 + 2 * lt;
                s[nf][0] += slope * (float)(kj - r0);
                s[nf][1] += slope * (float)(kj + 1 - r0);
                s[nf][2] += slope * (float)(kj - r1);
                s[nf][3] += slope * (float)(kj + 1 - r1);
                rmax0 = fmaxf(rmax0, fmaxf(s[nf][0], s[nf][1]));
                rmax1 = fmaxf(rmax1, fmaxf(s[nf][2], s[nf][3]));
            }
        } else {
            #pragma unroll
            for (int nf = 0; nf < 8; nf++) {
                int kj = k0 + nf * 8 + 2 * lt;
                int d00 = kj - r0, d01 = kj + 1 - r0;
                int d10 = kj - r1, d11 = kj + 1 - r1;
                s[nf][0] = (d00 <= 0) ? s[nf][0] + slope * (float)d00 : -1e30f;
                s[nf][1] = (d01 <= 0) ? s[nf][1] + slope * (float)d01 : -1e30f;
                s[nf][2] = (d10 <= 0) ? s[nf][2] + slope * (float)d10 : -1e30f;
                s[nf][3] = (d11 <= 0) ? s[nf][3] + slope * (float)d11 : -1e30f;
                rmax0 = fmaxf(rmax0, fmaxf(s[nf][0], s[nf][1]));
                rmax1 = fmaxf(rmax1, fmaxf(s[nf][2], s[nf][3]));
            }
        }
        rmax0 = fmaxf(rmax0, __shfl_xor_sync(0xffffffffu, rmax0, 1));
        rmax0 = fmaxf(rmax0, __shfl_xor_sync(0xffffffffu, rmax0, 2));
        rmax1 = fmaxf(rmax1, __shfl_xor_sync(0xffffffffu, rmax1, 1));
        rmax1 = fmaxf(rmax1, __shfl_xor_sync(0xffffffffu, rmax1, 2));

        float mn0 = fmaxf(m0, rmax0), mn1 = fmaxf(m1, rmax1);
        float c0 = ex2f(m0 - mn0),  c1 = ex2f(m1 - mn1);
        l0 *= c0; l1 *= c1;
        m0 = mn0; m1 = mn1;

        __syncthreads();   // all QK reads of Ks done before P overlay

        float rs0 = 0.f, rs1 = 0.f;
        #pragma unroll
        for (int nf = 0; nf < 8; nf++) {
            float p00 = ex2f(s[nf][0] - mn0);
            float p01 = ex2f(s[nf][1] - mn0);
            float p10 = ex2f(s[nf][2] - mn1);
            float p11 = ex2f(s[nf][3] - mn1);
            rs0 += p00 + p01;
            rs1 += p10 + p11;
            uint32_t* pr = &Pw[lg * SKW + nf * 8 + 2 * lt];
            uint2 u0 = { f2tf32(p00), f2tf32(p01) };
            uint2 u1 = { f2tf32(p10), f2tf32(p11) };
            *(uint2*)pr = u0;
            *(uint2*)(pr + 8 * SKW) = u1;
        }
        rs0 += __shfl_xor_sync(0xffffffffu, rs0, 1);
        rs0 += __shfl_xor_sync(0xffffffffu, rs0, 2);
        rs1 += __shfl_xor_sync(0xffffffffu, rs1, 1);
        rs1 += __shfl_xor_sync(0xffffffffu, rs1, 2);
        l0 += rs0; l1 += rs1;

        #pragma unroll
        for (int nf = 0; nf < 8; nf++) {
            oacc[nf][0] *= c0; oacc[nf][1] *= c0;
            oacc[nf][2] *= c1; oacc[nf][3] *= c1;
        }

        __syncwarp();

        #pragma unroll
        for (int ks = 0; ks < 8; ks++) {
            int kb = ks * 8;
            uint32_t a0 = Pw[lg * SKW + kb + lt];
            uint32_t a1 = Pw[(lg + 8) * SKW + kb + lt];
            uint32_t a2 = Pw[lg * SKW + kb + 4 + lt];
            uint32_t a3 = Pw[(lg + 8) * SKW + kb + 4 + lt];
            #pragma unroll
            for (int nf = 0; nf < 8; nf++) {
                int n = nf * 8 + lg;
                uint32_t b0 = Vs[(kb + lt) * SVW + n];
                uint32_t b1 = Vs[(kb + 4 + lt) * SVW + n];
                mma_tf32(oacc[nf], a0, a1, a2, a3, b0, b1);
            }
        }
    }

    // Final normalize + tf32-rounded store (g_o feeds the tf32 out-proj GEMM).
    float inv0 = 1.f / l0, inv1 = 1.f / l1;
    float* o0 = &g_o[((size_t)(b * T_ + r0)) * C_ + h * D_];
    float* o1 = &g_o[((size_t)(b * T_ + r1)) * C_ + h * D_];
    #pragma unroll
    for (int nf = 0; nf < 8; nf++) {
        int c = nf * 8 + 2 * lt;
        uint2 v0 = { f2tf32(oacc[nf][0] * inv0), f2tf32(oacc[nf][1] * inv0) };
        uint2 v1 = { f2tf32(oacc[nf][2] * inv1), f2tf32(oacc[nf][3] * inv1) };
        *(uint2*)&o0[c] = v0;
        *(uint2*)&o1[c] = v1;
    }
}

// ---------------------------------------------------------------------------
extern "C" void kernel_launch(void* const* d_in, const int* in_sizes, int n_in,
                              void* d_out, int out_size)
{
    const float* x  = (const float*)d_in[0];
    const float* Wq = (const float*)d_in[1];
    const float* bq = (const float*)d_in[2];
    const float* Wk = (const float*)d_in[3];
    const float* bk = (const float*)d_in[4];
    const float* Wv = (const float*)d_in[5];
    const float* bv = (const float*)d_in[6];
    const float* Wo = (const float*)d_in[7];
    const float* bo = (const float*)d_in[8];
    float* out = (float*)d_out;

    cudaFuncSetAttribute(qkv_gemm_kernel,
                         cudaFuncAttributeMaxDynamicSharedMemorySize, GEMM_SMEM);
    cudaFuncSetAttribute(out_gemm_kernel,
                         cudaFuncAttributeMaxDynamicSharedMemorySize, GEMM_SMEM);
    cudaFuncSetAttribute(attn_mma_kernel,
                         cudaFuncAttributeMaxDynamicSharedMemorySize, ATT_SMEM);

    conv_kernel<<<2048, 256>>>(x, Wq, Wk, Wv, Wo);

    qkv_gemm_kernel<<<dim3(24, 32), 256, GEMM_SMEM>>>(bq, bk, bv);

    attn_mma_kernel<<<dim3(T_ / 64, H_, B_), 128, ATT_SMEM>>>();

    out_gemm_kernel<<<dim3(8, 32), 256, GEMM_SMEM>>>(bo, out);
}

// round 7
// speedup vs baseline: 4.6595x; 1.0392x over previous
#include <cuda_runtime.h>
#include <stdint.h>
#include <math.h>

#define B_ 2
#define T_ 2048
#define C_ 1024
#define H_ 16
#define D_ 64
#define M_ (B_*T_)   // 4096 rows

// Scratch (allocation-free).
__device__ float g_q[M_*C_];
__device__ float g_k[M_*C_];
__device__ float g_v[M_*C_];
__device__ float g_o[M_*C_];
__device__ float g_xt[M_*C_];      // tf32-rounded x
__device__ float g_wt[4*C_*C_];    // tf32-rounded Wq,Wk,Wv,Wo

__device__ __forceinline__ uint32_t f2tf32(float x) {
    uint32_t u;
    asm("cvt.rna.tf32.f32 %0, %1;" : "=r"(u) : "f"(x));
    return u;
}

__device__ __forceinline__ float ex2f(float x) {
    float y;
    asm("ex2.approx.ftz.f32 %0, %1;" : "=f"(y) : "f"(x));
    return y;
}

__device__ __forceinline__ void mma_tf32(float c[4],
    uint32_t a0, uint32_t a1, uint32_t a2, uint32_t a3,
    uint32_t b0, uint32_t b1)
{
    asm volatile(
        "mma.sync.aligned.m16n8k8.row.col.f32.tf32.tf32.f32 "
        "{%0,%1,%2,%3},{%4,%5,%6,%7},{%8,%9},{%0,%1,%2,%3};"
        : "+f"(c[0]), "+f"(c[1]), "+f"(c[2]), "+f"(c[3])
        : "r"(a0), "r"(a1), "r"(a2), "r"(a3), "r"(b0), "r"(b1));
}

__device__ __forceinline__ void cpa16(void* dst, const void* src) {
    uint32_t d = (uint32_t)__cvta_generic_to_shared(dst);
    asm volatile("cp.async.cg.shared.global [%0], [%1], 16;" :: "r"(d), "l"(src));
}
#define CP_COMMIT() asm volatile("cp.async.commit_group;")
#define CP_WAIT(N)  asm volatile("cp.async.wait_group %0;" :: "n"(N))

// ---------------------------------------------------------------------------
// Pre-round x and the 4 weight matrices to tf32 (rna) once.
// ---------------------------------------------------------------------------
__global__ __launch_bounds__(256) void conv_kernel(
    const float* __restrict__ x,  const float* __restrict__ Wq,
    const float* __restrict__ Wk, const float* __restrict__ Wv,
    const float* __restrict__ Wo)
{
    const float* Ws[4] = { Wq, Wk, Wv, Wo };
    int base = blockIdx.x * 256 + threadIdx.x;
    #pragma unroll
    for (int l = 0; l < 4; l++) {
        int i4 = base + l * (2048 * 256);
        int r  = i4 >> 18;
        const float* src;
        float* dst;
        if (r < 4) { src = x + ((size_t)i4 << 2); dst = g_xt + ((size_t)i4 << 2); }
        else {
            int off = i4 & 0x3FFFF;
            src = Ws[r - 4] + ((size_t)off << 2);
            dst = g_wt + ((size_t)(r - 4) << 20) + ((size_t)off << 2);
        }
        float4 v = *(const float4*)src;
        uint4 u = { f2tf32(v.x), f2tf32(v.y), f2tf32(v.z), f2tf32(v.w) };
        *(uint4*)dst = u;
    }
}

// ---------------------------------------------------------------------------
// 3-stage cp.async TF32 GEMM: C = A @ W + bias. A,W pre-rounded tf32.
// ---------------------------------------------------------------------------
#define BM 128
#define BN 128
#define BK 32
#define SA 36
#define SB 136
#define STG_W (BM*SA + BK*SB)       // 8960 words
#define GEMM_SMEM (3*STG_W*4)       // 107520 bytes

__device__ __forceinline__ void gemm_issue(
    uint32_t* stage, const float* A, const float* W,
    int brow, int bcol, int k0, int tid)
{
    uint32_t* As = stage;
    uint32_t* Ws = stage + BM * SA;
    #pragma unroll
    for (int l = 0; l < 4; l++) {
        int f4 = tid + (l << 8);
        int ar = f4 >> 3, ac = (f4 & 7) << 2;
        cpa16(&As[ar * SA + ac], &A[(size_t)(brow + ar) * C_ + k0 + ac]);
        int wr_ = f4 >> 5, wc_ = (f4 & 31) << 2;
        cpa16(&Ws[wr_ * SB + wc_], &W[(size_t)(k0 + wr_) * C_ + bcol + wc_]);
    }
}

__device__ __forceinline__ void gemm_pipe(
    const float* __restrict__ A, const float* __restrict__ W,
    const float* __restrict__ bias, float* __restrict__ Cm,
    int brow, int bcol, int roundOut)
{
    extern __shared__ uint32_t smem[];
    const int tid  = threadIdx.x;
    const int lane = tid & 31;
    const int warp = tid >> 5;
    const int wr   = warp >> 2;
    const int wc   = warp & 3;
    const int lg   = lane >> 2;
    const int lt   = lane & 3;

    float acc[4][4][4];
    #pragma unroll
    for (int mf = 0; mf < 4; mf++)
        #pragma unroll
        for (int nf = 0; nf < 4; nf++)
            #pragma unroll
            for (int r = 0; r < 4; r++) acc[mf][nf][r] = 0.f;

    gemm_issue(smem,         A, W, brow, bcol, 0,  tid); CP_COMMIT();
    gemm_issue(smem + STG_W, A, W, brow, bcol, BK, tid); CP_COMMIT();

    const int NIT = C_ / BK;   // 32
    #pragma unroll 1
    for (int it = 0; it < NIT; it++) {
        CP_WAIT(1);
        __syncthreads();
        int kn = (it + 2) * BK;
        if (kn < C_) gemm_issue(smem + ((it + 2) % 3) * STG_W, A, W, brow, bcol, kn, tid);
        CP_COMMIT();

        const uint32_t* As = smem + (it % 3) * STG_W;
        const uint32_t* Ws = As + BM * SA;
        #pragma unroll
        for (int ks = 0; ks < 4; ks++) {
            const int kb = ks * 8;
            uint32_t bf[4][2];
            #pragma unroll
            for (int nf = 0; nf < 4; nf++) {
                int n = wc * 32 + nf * 8 + lg;
                bf[nf][0] = Ws[(kb + lt) * SB + n];
                bf[nf][1] = Ws[(kb + 4 + lt) * SB + n];
            }
            #pragma unroll
            for (int mf = 0; mf < 4; mf++) {
                int m0 = wr * 64 + mf * 16 + lg;
                uint32_t a0 = As[m0 * SA + kb + lt];
                uint32_t a1 = As[(m0 + 8) * SA + kb + lt];
                uint32_t a2 = As[m0 * SA + kb + 4 + lt];
                uint32_t a3 = As[(m0 + 8) * SA + kb + 4 + lt];
                #pragma unroll
                for (int nf = 0; nf < 4; nf++)
                    mma_tf32(acc[mf][nf], a0, a1, a2, a3, bf[nf][0], bf[nf][1]);
            }
        }
    }

    #pragma unroll
    for (int mf = 0; mf < 4; mf++) {
        int row0 = brow + wr * 64 + mf * 16 + lg;
        #pragma unroll
        for (int nf = 0; nf < 4; nf++) {
            int col = bcol + wc * 32 + nf * 8 + lt * 2;
            float bx = bias[col], by = bias[col + 1];
            float v00 = acc[mf][nf][0] + bx, v01 = acc[mf][nf][1] + by;
            float v10 = acc[mf][nf][2] + bx, v11 = acc[mf][nf][3] + by;
            if (roundOut) {
                uint2 o0 = { f2tf32(v00), f2tf32(v01) };
                uint2 o1 = { f2tf32(v10), f2tf32(v11) };
                *(uint2*)&Cm[(size_t)row0 * C_ + col]       = o0;
                *(uint2*)&Cm[(size_t)(row0 + 8) * C_ + col] = o1;
            } else {
                float2 o0 = { v00, v01 };
                float2 o1 = { v10, v11 };
                *(float2*)&Cm[(size_t)row0 * C_ + col]       = o0;
                *(float2*)&Cm[(size_t)(row0 + 8) * C_ + col] = o1;
            }
        }
    }
}

__global__ __launch_bounds__(256) void qkv_gemm_kernel(
    const float* __restrict__ bq, const float* __restrict__ bk,
    const float* __restrict__ bv)
{
    int sel  = blockIdx.x >> 3;
    int bcol = (blockIdx.x & 7) * BN;
    int brow = blockIdx.y * BM;
    const float* W    = g_wt + ((size_t)sel << 20);
    const float* bias = (sel == 0) ? bq : (sel == 1) ? bk : bv;
    float* Cm         = (sel == 0) ? g_q : (sel == 1) ? g_k : g_v;
    gemm_pipe(g_xt, W, bias, Cm, brow, bcol, 1);
}

__global__ __launch_bounds__(256) void out_gemm_kernel(
    const float* __restrict__ bo, float* __restrict__ out)
{
    gemm_pipe(g_o, g_wt + ((size_t)3 << 20), bo, out,
              blockIdx.y * BM, blockIdx.x * BN, 0);
}

// ---------------------------------------------------------------------------
// TF32 flash attention, ALiBi + causal. 128 thr (4 warps), warp owns 32 query
// rows (two m16 fragment groups sharing B-fragments). CTA covers 128 queries.
// cp.async double-buffered 64-key K/V tiles; dedicated P region in SMEM.
// Heavy CTAs (large qbase) launched first via index reversal.
// ---------------------------------------------------------------------------
#define AKT 64
#define SKW 68
#define SVW 72
#define AST_W (AKT*SKW + AKT*SVW)          // 8960 words per stage
#define PS_W  (128*SKW)                    // 8704 words
#define ATT_SMEM ((2*AST_W + PS_W)*4)      // 106496 bytes

__device__ __forceinline__ void attn_issue_kv(
    uint32_t* stage, int b, int h, int k0, int tid)
{
    uint32_t* Ks = stage;
    uint32_t* Vs = stage + AKT * SKW;
    #pragma unroll
    for (int l = 0; l < 8; l++) {
        int f4 = tid + l * 128;
        int r  = f4 >> 4;
        int c4 = (f4 & 15) << 2;
        size_t base = ((size_t)(b * T_ + k0 + r)) * C_ + h * D_ + c4;
        cpa16(&Ks[r * SKW + c4], &g_k[base]);
        cpa16(&Vs[r * SVW + c4], &g_v[base]);
    }
}

__global__ __launch_bounds__(128) void attn_mma_kernel()
{
    extern __shared__ uint32_t sm[];
    uint32_t* Ps = sm + 2 * AST_W;

    const int tid  = threadIdx.x;
    const int lane = tid & 31;
    const int warp = tid >> 5;
    const int lg   = lane >> 2;
    const int lt   = lane & 3;
    const int h    = blockIdx.y;
    const int b    = blockIdx.z;
    const int qbase = (gridDim.x - 1 - blockIdx.x) * 128;   // heavy-first

    const float LOG2E = 1.4426950408889634f;
    const float scale = 0.125f * LOG2E;
    const float slope = exp2f(-0.5f * (float)(h + 1)) * LOG2E;

    const int wmin = qbase + warp * 32;
    const int r00 = wmin + lg;        // mg0 rows: r00, r00+8
    const int r10 = wmin + 16 + lg;   // mg1 rows: r10, r10+8

    // Q fragments, scale folded. qf[mg][ks] = {A[r0][c], A[r0+8][c], A[r0][c+4], A[r0+8][c+4]}
    uint32_t qf[2][8][4];
    {
        const float* qa = &g_q[((size_t)(b * T_ + r00)) * C_ + h * D_];
        const float* qb = &g_q[((size_t)(b * T_ + r00 + 8)) * C_ + h * D_];
        const float* qc = &g_q[((size_t)(b * T_ + r10)) * C_ + h * D_];
        const float* qd = &g_q[((size_t)(b * T_ + r10 + 8)) * C_ + h * D_];
        #pragma unroll
        for (int ks = 0; ks < 8; ks++) {
            int c = ks * 8 + lt;
            qf[0][ks][0] = f2tf32(qa[c] * scale);
            qf[0][ks][1] = f2tf32(qb[c] * scale);
            qf[0][ks][2] = f2tf32(qa[c + 4] * scale);
            qf[0][ks][3] = f2tf32(qb[c + 4] * scale);
            qf[1][ks][0] = f2tf32(qc[c] * scale);
            qf[1][ks][1] = f2tf32(qd[c] * scale);
            qf[1][ks][2] = f2tf32(qc[c + 4] * scale);
            qf[1][ks][3] = f2tf32(qd[c + 4] * scale);
        }
    }

    float oacc[2][8][4];
    #pragma unroll
    for (int mg = 0; mg < 2; mg++)
        #pragma unroll
        for (int nf = 0; nf < 8; nf++)
            #pragma unroll
            for (int r = 0; r < 4; r++) oacc[mg][nf][r] = 0.f;
    float mrow[2][2] = { {-1e30f, -1e30f}, {-1e30f, -1e30f} };
    float lrow[2][2] = { {0.f, 0.f}, {0.f, 0.f} };

    const int ntiles = qbase / AKT + 2;
    uint32_t* Pw = Ps + warp * 32 * SKW;

    attn_issue_kv(sm, b, h, 0, tid); CP_COMMIT();

    #pragma unroll 1
    for (int t = 0; t < ntiles; t++) {
        CP_WAIT(0);
        __syncthreads();
        if (t + 1 < ntiles)
            attn_issue_kv(sm + ((t + 1) & 1) * AST_W, b, h, (t + 1) * AKT, tid);
        CP_COMMIT();

        const int k0 = t * AKT;
        if (k0 > wmin + 31) continue;   // tile fully masked for this warp

        uint32_t* Ks = sm + (t & 1) * AST_W;
        uint32_t* Vs = Ks + AKT * SKW;

        // S = Q K^T  (32x64 per warp, shared B-fragments)
        float s[2][8][4];
        #pragma unroll
        for (int mg = 0; mg < 2; mg++)
            #pragma unroll
            for (int nf = 0; nf < 8; nf++)
                #pragma unroll
                for (int r = 0; r < 4; r++) s[mg][nf][r] = 0.f;

        #pragma unroll
        for (int ks = 0; ks < 8; ks++) {
            int kb = ks * 8;
            uint32_t bf0[8], bf1[8];
            #pragma unroll
            for (int nf = 0; nf < 8; nf++) {
                int n = nf * 8 + lg;
                bf0[nf] = Ks[n * SKW + kb + lt];
                bf1[nf] = Ks[n * SKW + kb + 4 + lt];
            }
            #pragma unroll
            for (int nf = 0; nf < 8; nf++)
                mma_tf32(s[0][nf], qf[0][ks][0], qf[0][ks][1], qf[0][ks][2], qf[0][ks][3], bf0[nf], bf1[nf]);
            #pragma unroll
            for (int nf = 0; nf < 8; nf++)
                mma_tf32(s[1][nf], qf[1][ks][0], qf[1][ks][1], qf[1][ks][2], qf[1][ks][3], bf0[nf], bf1[nf]);
        }

        // ALiBi + causal + row max
        float rmax[2][2] = { {-1e30f, -1e30f}, {-1e30f, -1e30f} };
        if (k0 + AKT - 1 <= wmin) {
            #pragma unroll
            for (int mg = 0; mg < 2; mg++) {
                int ra = mg ? r10 : r00;
                #pragma unroll
                for (int nf = 0; nf < 8; nf++) {
                    int kj = k0 + nf * 8 + 2 * lt;
                    s[mg][nf][0] += slope * (float)(kj - ra);
                    s[mg][nf][1] += slope * (float)(kj + 1 - ra);
                    s[mg][nf][2] += slope * (float)(kj - (ra + 8));
                    s[mg][nf][3] += slope * (float)(kj + 1 - (ra + 8));
                    rmax[mg][0] = fmaxf(rmax[mg][0], fmaxf(s[mg][nf][0], s[mg][nf][1]));
                    rmax[mg][1] = fmaxf(rmax[mg][1], fmaxf(s[mg][nf][2], s[mg][nf][3]));
                }
            }
        } else {
            #pragma unroll
            for (int mg = 0; mg < 2; mg++) {
                int ra = mg ? r10 : r00;
                #pragma unroll
                for (int nf = 0; nf < 8; nf++) {
                    int kj = k0 + nf * 8 + 2 * lt;
                    int d00 = kj - ra, d01 = kj + 1 - ra;
                    int d10 = kj - (ra + 8), d11 = kj + 1 - (ra + 8);
                    s[mg][nf][0] = (d00 <= 0) ? s[mg][nf][0] + slope * (float)d00 : -1e30f;
                    s[mg][nf][1] = (d01 <= 0) ? s[mg][nf][1] + slope * (float)d01 : -1e30f;
                    s[mg][nf][2] = (d10 <= 0) ? s[mg][nf][2] + slope * (float)d10 : -1e30f;
                    s[mg][nf][3] = (d11 <= 0) ? s[mg][nf][3] + slope * (float)d11 : -1e30f;
                    rmax[mg][0] = fmaxf(rmax[mg][0], fmaxf(s[mg][nf][0], s[mg][nf][1]));
                    rmax[mg][1] = fmaxf(rmax[mg][1], fmaxf(s[mg][nf][2], s[mg][nf][3]));
                }
            }
        }
        #pragma unroll
        for (int mg = 0; mg < 2; mg++)
            #pragma unroll
            for (int hh = 0; hh < 2; hh++) {
                float v = rmax[mg][hh];
                v = fmaxf(v, __shfl_xor_sync(0xffffffffu, v, 1));
                v = fmaxf(v, __shfl_xor_sync(0xffffffffu, v, 2));
                rmax[mg][hh] = v;
            }

        float corr[2][2], mn[2][2];
        #pragma unroll
        for (int mg = 0; mg < 2; mg++)
            #pragma unroll
            for (int hh = 0; hh < 2; hh++) {
                mn[mg][hh] = fmaxf(mrow[mg][hh], rmax[mg][hh]);
                corr[mg][hh] = ex2f(mrow[mg][hh] - mn[mg][hh]);
                lrow[mg][hh] *= corr[mg][hh];
                mrow[mg][hh] = mn[mg][hh];
            }

        // P = exp2(S - m) -> SMEM (tf32), row sums
        float rs[2][2] = { {0.f, 0.f}, {0.f, 0.f} };
        #pragma unroll
        for (int mg = 0; mg < 2; mg++) {
            int row0 = mg * 16 + lg;
            #pragma unroll
            for (int nf = 0; nf < 8; nf++) {
                float p0 = ex2f(s[mg][nf][0] - mn[mg][0]);
                float p1 = ex2f(s[mg][nf][1] - mn[mg][0]);
                float p2 = ex2f(s[mg][nf][2] - mn[mg][1]);
                float p3 = ex2f(s[mg][nf][3] - mn[mg][1]);
                rs[mg][0] += p0 + p1;
                rs[mg][1] += p2 + p3;
                uint32_t* pr = &Pw[row0 * SKW + nf * 8 + 2 * lt];
                uint2 u0 = { f2tf32(p0), f2tf32(p1) };
                uint2 u1 = { f2tf32(p2), f2tf32(p3) };
                *(uint2*)pr = u0;
                *(uint2*)(pr + 8 * SKW) = u1;
            }
        }
        #pragma unroll
        for (int mg = 0; mg < 2; mg++)
            #pragma unroll
            for (int hh = 0; hh < 2; hh++) {
                float v = rs[mg][hh];
                v += __shfl_xor_sync(0xffffffffu, v, 1);
                v += __shfl_xor_sync(0xffffffffu, v, 2);
                lrow[mg][hh] += v;
            }

        #pragma unroll
        for (int mg = 0; mg < 2; mg++)
            #pragma unroll
            for (int nf = 0; nf < 8; nf++) {
                oacc[mg][nf][0] *= corr[mg][0];
                oacc[mg][nf][1] *= corr[mg][0];
                oacc[mg][nf][2] *= corr[mg][1];
                oacc[mg][nf][3] *= corr[mg][1];
            }

        __syncwarp();

        // O += P V (shared B-fragments across mg)
        #pragma unroll
        for (int ks = 0; ks < 8; ks++) {
            int kb = ks * 8;
            uint32_t bf0[8], bf1[8];
            #pragma unroll
            for (int nf = 0; nf < 8; nf++) {
                int n = nf * 8 + lg;
                bf0[nf] = Vs[(kb + lt) * SVW + n];
                bf1[nf] = Vs[(kb + 4 + lt) * SVW + n];
            }
            #pragma unroll
            for (int mg = 0; mg < 2; mg++) {
                int row0 = mg * 16 + lg;
                uint32_t a0 = Pw[row0 * SKW + kb + lt];
                uint32_t a1 = Pw[(row0 + 8) * SKW + kb + lt];
                uint32_t a2 = Pw[row0 * SKW + kb + 4 + lt];
                uint32_t a3 = Pw[(row0 + 8) * SKW + kb + 4 + lt];
                #pragma unroll
                for (int nf = 0; nf < 8; nf++)
                    mma_tf32(oacc[mg][nf], a0, a1, a2, a3, bf0[nf], bf1[nf]);
            }
        }
    }

    // Final normalize + tf32-rounded store (g_o feeds tf32 out-proj GEMM).
    #pragma unroll
    for (int mg = 0; mg < 2; mg++) {
        int ra = mg ? r10 : r00;
        float inv0 = 1.f / lrow[mg][0], inv1 = 1.f / lrow[mg][1];
        float* o0 = &g_o[((size_t)(b * T_ + ra)) * C_ + h * D_];
        float* o1 = &g_o[((size_t)(b * T_ + ra + 8)) * C_ + h * D_];
        #pragma unroll
        for (int nf = 0; nf < 8; nf++) {
            int c = nf * 8 + 2 * lt;
            uint2 v0 = { f2tf32(oacc[mg][nf][0] * inv0), f2tf32(oacc[mg][nf][1] * inv0) };
            uint2 v1 = { f2tf32(oacc[mg][nf][2] * inv1), f2tf32(oacc[mg][nf][3] * inv1) };
            *(uint2*)&o0[c] = v0;
            *(uint2*)&o1[c] = v1;
        }
    }
}

// ---------------------------------------------------------------------------
extern "C" void kernel_launch(void* const* d_in, const int* in_sizes, int n_in,
                              void* d_out, int out_size)
{
    const float* x  = (const float*)d_in[0];
    const float* Wq = (const float*)d_in[1];
    const float* bq = (const float*)d_in[2];
    const float* Wk = (const float*)d_in[3];
    const float* bk = (const float*)d_in[4];
    const float* Wv = (const float*)d_in[5];
    const float* bv = (const float*)d_in[6];
    const float* Wo = (const float*)d_in[7];
    const float* bo = (const float*)d_in[8];
    float* out = (float*)d_out;

    cudaFuncSetAttribute(qkv_gemm_kernel,
                         cudaFuncAttributeMaxDynamicSharedMemorySize, GEMM_SMEM);
    cudaFuncSetAttribute(out_gemm_kernel,
                         cudaFuncAttributeMaxDynamicSharedMemorySize, GEMM_SMEM);
    cudaFuncSetAttribute(attn_mma_kernel,
                         cudaFuncAttributeMaxDynamicSharedMemorySize, ATT_SMEM);

    conv_kernel<<<2048, 256>>>(x, Wq, Wk, Wv, Wo);

    qkv_gemm_kernel<<<dim3(24, 32), 256, GEMM_SMEM>>>(bq, bk, bv);

    attn_mma_kernel<<<dim3(T_ / 128, H_, B_), 128, ATT_SMEM>>>();

    out_gemm_kernel<<<dim3(8, 32), 256, GEMM_SMEM>>>(bo, out);
}

// round 8
// speedup vs baseline: 4.7551x; 1.0205x over previous
#include <cuda_runtime.h>
#include <stdint.h>
#include <math.h>

#define B_ 2
#define T_ 2048
#define C_ 1024
#define H_ 16
#define D_ 64
#define M_ (B_*T_)   // 4096 rows

// Scratch (allocation-free).
__device__ float g_q[M_*C_];
__device__ float g_k[M_*C_];
__device__ float g_v[M_*C_];
__device__ float g_vt[M_*C_];      // V transposed: [b][h][d][t]
__device__ float g_o[M_*C_];
__device__ float g_xt[M_*C_];      // tf32-rounded x
__device__ float g_wt[4*C_*C_];    // tf32-rounded W^T: [sel][n][k]

__device__ __forceinline__ uint32_t f2tf32(float x) {
    uint32_t u;
    asm("cvt.rna.tf32.f32 %0, %1;" : "=r"(u) : "f"(x));
    return u;
}

__device__ __forceinline__ float ex2f(float x) {
    float y;
    asm("ex2.approx.ftz.f32 %0, %1;" : "=f"(y) : "f"(x));
    return y;
}

__device__ __forceinline__ void mma_tf32(float c[4],
    uint32_t a0, uint32_t a1, uint32_t a2, uint32_t a3,
    uint32_t b0, uint32_t b1)
{
    asm volatile(
        "mma.sync.aligned.m16n8k8.row.col.f32.tf32.tf32.f32 "
        "{%0,%1,%2,%3},{%4,%5,%6,%7},{%8,%9},{%0,%1,%2,%3};"
        : "+f"(c[0]), "+f"(c[1]), "+f"(c[2]), "+f"(c[3])
        : "r"(a0), "r"(a1), "r"(a2), "r"(a3), "r"(b0), "r"(b1));
}

__device__ __forceinline__ void ldsm4(uint32_t r[4], uint32_t saddr) {
    asm volatile("ldmatrix.sync.aligned.m8n8.x4.shared.b16 {%0,%1,%2,%3}, [%4];"
        : "=r"(r[0]), "=r"(r[1]), "=r"(r[2]), "=r"(r[3]) : "r"(saddr));
}

__device__ __forceinline__ void cpa16(void* dst, const void* src) {
    uint32_t d = (uint32_t)__cvta_generic_to_shared(dst);
    asm volatile("cp.async.cg.shared.global [%0], [%1], 16;" :: "r"(d), "l"(src));
}
#define CP_COMMIT() asm volatile("cp.async.commit_group;")
#define CP_WAIT(N)  asm volatile("cp.async.wait_group %0;" :: "n"(N))

// ---------------------------------------------------------------------------
// conv_x: round x -> g_xt (tf32). 1M float4; grid 1024 x 256thr x 4.
// ---------------------------------------------------------------------------
__global__ __launch_bounds__(256) void conv_x_kernel(const float* __restrict__ x)
{
    #pragma unroll
    for (int l = 0; l < 4; l++) {
        int i4 = blockIdx.x * 1024 + l * 256 + threadIdx.x;
        float4 v = *(const float4*)&x[(size_t)i4 << 2];
        uint4 u = { f2tf32(v.x), f2tf32(v.y), f2tf32(v.z), f2tf32(v.w) };
        *(uint4*)&g_xt[(size_t)i4 << 2] = u;
    }
}

// ---------------------------------------------------------------------------
// conv_w: round + TRANSPOSE the 4 weight matrices: g_wt[sel][n][k] = W[k][n].
// 64x64 tiles; grid 4*256 blocks.
// ---------------------------------------------------------------------------
__global__ __launch_bounds__(256) void conv_w_kernel(
    const float* __restrict__ Wq, const float* __restrict__ Wk,
    const float* __restrict__ Wv, const float* __restrict__ Wo)
{
    __shared__ float tile[64][65];
    const float* Ws[4] = { Wq, Wk, Wv, Wo };
    int mat = blockIdx.x >> 8;
    int t   = blockIdx.x & 255;
    int kb  = (t >> 4) << 6;
    int nb  = (t & 15) << 6;
    const float* W = Ws[mat];
    int tid = threadIdx.x;
    int rr = tid >> 4, c4 = (tid & 15) << 2;
    #pragma unroll
    for (int l = 0; l < 4; l++) {
        int row = rr + l * 16;
        float4 v = *(const float4*)&W[(size_t)(kb + row) * C_ + nb + c4];
        tile[row][c4 + 0] = __uint_as_float(f2tf32(v.x));
        tile[row][c4 + 1] = __uint_as_float(f2tf32(v.y));
        tile[row][c4 + 2] = __uint_as_float(f2tf32(v.z));
        tile[row][c4 + 3] = __uint_as_float(f2tf32(v.w));
    }
    __syncthreads();
    float* dst = g_wt + ((size_t)mat << 20);
    #pragma unroll
    for (int l = 0; l < 4; l++) {
        int row = rr + l * 16;   // n index
        float4 o = { tile[c4 + 0][row], tile[c4 + 1][row],
                     tile[c4 + 2][row], tile[c4 + 3][row] };
        *(float4*)&dst[(size_t)(nb + row) * C_ + kb + c4] = o;
    }
}

// ---------------------------------------------------------------------------
// vt: transpose V per (b,h): g_vt[((b*H+h)*D+d)*T + t] = g_v[(b*T+t)*C + h*D+d]
// grid (32,16,2), 256 thr.
// ---------------------------------------------------------------------------
__global__ __launch_bounds__(256) void vt_kernel()
{
    __shared__ float tile[64][65];
    int t0 = blockIdx.x * 64;
    int h  = blockIdx.y;
    int b  = blockIdx.z;
    int tid = threadIdx.x;
    int rr = tid >> 4, c4 = (tid & 15) << 2;
    #pragma unroll
    for (int l = 0; l < 4; l++) {
        int row = rr + l * 16;   // t offset
        float4 v = *(const float4*)&g_v[(size_t)(b * T_ + t0 + row) * C_ + h * D_ + c4];
        tile[row][c4 + 0] = v.x; tile[row][c4 + 1] = v.y;
        tile[row][c4 + 2] = v.z; tile[row][c4 + 3] = v.w;
    }
    __syncthreads();
    #pragma unroll
    for (int l = 0; l < 4; l++) {
        int row = rr + l * 16;   // d index
        float4 o = { tile[c4 + 0][row], tile[c4 + 1][row],
                     tile[c4 + 2][row], tile[c4 + 3][row] };
        *(float4*)&g_vt[((size_t)((b * H_ + h) * D_ + row)) * T_ + t0 + c4] = o;
    }
}

// ---------------------------------------------------------------------------
// 3-stage cp.async TF32 GEMM with ldmatrix fragments.
// C[M,N] = A[M,K] @ W[K,N] + bias.  A row-major [m][k], Wt row-major [n][k].
// 128x128 tile, BK=32, 256 thr (8 warps 2x4), warp 64x32.
// ---------------------------------------------------------------------------
#define BM 128
#define BN 128
#define BK 32
#define SA 36
#define STG_W (2*BM*SA)            // 9216 words per stage (A + Wt)
#define GEMM_SMEM (3*STG_W*4)      // 110592 bytes

__device__ __forceinline__ void gemm_issue(
    uint32_t* stage, const float* A, const float* Wt,
    int brow, int bcol, int k0, int tid)
{
    uint32_t* As = stage;
    uint32_t* Ws = stage + BM * SA;
    #pragma unroll
    for (int l = 0; l < 4; l++) {
        int f4 = tid + (l << 8);
        int r = f4 >> 3, c = (f4 & 7) << 2;
        cpa16(&As[r * SA + c], &A [(size_t)(brow + r) * C_ + k0 + c]);
        cpa16(&Ws[r * SA + c], &Wt[(size_t)(bcol + r) * C_ + k0 + c]);
    }
}

__device__ __forceinline__ void gemm_pipe(
    const float* __restrict__ A, const float* __restrict__ Wt,
    const float* __restrict__ bias, float* __restrict__ Cm,
    int brow, int bcol, int roundOut)
{
    extern __shared__ uint32_t smem[];
    const int tid  = threadIdx.x;
    const int lane = tid & 31;
    const int warp = tid >> 5;
    const int wr   = warp >> 2;
    const int wc   = warp & 3;
    const int lg   = lane >> 2;
    const int lt   = lane & 3;

    // ldmatrix per-thread row/col offsets
    const int arow = (lane & 7) + ((lane >> 3) & 1) * 8;
    const int acol = ((lane >> 4) & 1) * 4;
    const int brw  = (lane & 7) + ((lane >> 4) & 1) * 8;
    const int bcl  = ((lane >> 3) & 1) * 4;
    const uint32_t smem_u32 = (uint32_t)__cvta_generic_to_shared(smem);

    float acc[4][4][4];
    #pragma unroll
    for (int mf = 0; mf < 4; mf++)
        #pragma unroll
        for (int nf = 0; nf < 4; nf++)
            #pragma unroll
            for (int r = 0; r < 4; r++) acc[mf][nf][r] = 0.f;

    gemm_issue(smem,         A, Wt, brow, bcol, 0,  tid); CP_COMMIT();
    gemm_issue(smem + STG_W, A, Wt, brow, bcol, BK, tid); CP_COMMIT();

    const int NIT = C_ / BK;   // 32
    #pragma unroll 1
    for (int it = 0; it < NIT; it++) {
        CP_WAIT(1);
        __syncthreads();
        int kn = (it + 2) * BK;
        if (kn < C_) gemm_issue(smem + ((it + 2) % 3) * STG_W, A, Wt, brow, bcol, kn, tid);
        CP_COMMIT();

        uint32_t sbase = smem_u32 + (uint32_t)((it % 3) * STG_W) * 4u;
        uint32_t aaddr = sbase + (uint32_t)((wr * 64 + arow) * SA + acol) * 4u;
        uint32_t baddr = sbase + (uint32_t)(BM * SA + (wc * 32 + brw) * SA + bcl) * 4u;

        #pragma unroll
        for (int ks = 0; ks < 4; ks++) {
            const int kb = ks * 8;
            uint32_t b01[4], b23[4];
            ldsm4(b01, baddr + (uint32_t)kb * 4u);
            ldsm4(b23, baddr + (uint32_t)(16 * SA + kb) * 4u);
            #pragma unroll
            for (int mf = 0; mf < 4; mf++) {
                uint32_t a[4];
                ldsm4(a, aaddr + (uint32_t)(mf * 16 * SA + kb) * 4u);
                mma_tf32(acc[mf][0], a[0], a[1], a[2], a[3], b01[0], b01[1]);
                mma_tf32(acc[mf][1], a[0], a[1], a[2], a[3], b01[2], b01[3]);
                mma_tf32(acc[mf][2], a[0], a[1], a[2], a[3], b23[0], b23[1]);
                mma_tf32(acc[mf][3], a[0], a[1], a[2], a[3], b23[2], b23[3]);
            }
        }
    }

    #pragma unroll
    for (int mf = 0; mf < 4; mf++) {
        int row0 = brow + wr * 64 + mf * 16 + lg;
        #pragma unroll
        for (int nf = 0; nf < 4; nf++) {
            int col = bcol + wc * 32 + nf * 8 + lt * 2;
            float bx = bias[col], by = bias[col + 1];
            float v00 = acc[mf][nf][0] + bx, v01 = acc[mf][nf][1] + by;
            float v10 = acc[mf][nf][2] + bx, v11 = acc[mf][nf][3] + by;
            if (roundOut) {
                uint2 o0 = { f2tf32(v00), f2tf32(v01) };
                uint2 o1 = { f2tf32(v10), f2tf32(v11) };
                *(uint2*)&Cm[(size_t)row0 * C_ + col]       = o0;
                *(uint2*)&Cm[(size_t)(row0 + 8) * C_ + col] = o1;
            } else {
                float2 o0 = { v00, v01 };
                float2 o1 = { v10, v11 };
                *(float2*)&Cm[(size_t)row0 * C_ + col]       = o0;
                *(float2*)&Cm[(size_t)(row0 + 8) * C_ + col] = o1;
            }
        }
    }
}

__global__ __launch_bounds__(256) void qkv_gemm_kernel(
    const float* __restrict__ bq, const float* __restrict__ bk,
    const float* __restrict__ bv)
{
    int sel  = blockIdx.x >> 3;
    int bcol = (blockIdx.x & 7) * BN;
    int brow = blockIdx.y * BM;
    const float* Wt   = g_wt + ((size_t)sel << 20);
    const float* bias = (sel == 0) ? bq : (sel == 1) ? bk : bv;
    float* Cm         = (sel == 0) ? g_q : (sel == 1) ? g_k : g_v;
    gemm_pipe(g_xt, Wt, bias, Cm, brow, bcol, 1);
}

__global__ __launch_bounds__(256) void out_gemm_kernel(
    const float* __restrict__ bo, float* __restrict__ out)
{
    gemm_pipe(g_o, g_wt + ((size_t)3 << 20), bo, out,
              blockIdx.y * BM, blockIdx.x * BN, 0);
}

// ---------------------------------------------------------------------------
// TF32 flash attention with ldmatrix fragments everywhere.
// 128 thr (4 warps), warp owns 32 query rows. CTA covers 128 queries.
// K tiles natural [key][dim]; V tiles from g_vt as [dim][key].
// ---------------------------------------------------------------------------
#define AKT 64
#define SKW 68
#define SVW 68
#define SPW 68
#define AST_W (AKT*SKW + AKT*SVW)          // 8704 words per stage
#define PS_W  (128*SPW)                    // 8704 words
#define ATT_SMEM ((2*AST_W + PS_W)*4)      // 104448 bytes

__device__ __forceinline__ void attn_issue_kv(
    uint32_t* stage, int b, int h, int k0, int tid)
{
    uint32_t* Ks = stage;
    uint32_t* Vs = stage + AKT * SKW;
    #pragma unroll
    for (int l = 0; l < 8; l++) {
        int f4 = tid + l * 128;
        int r  = f4 >> 4;
        int c4 = (f4 & 15) << 2;
        cpa16(&Ks[r * SKW + c4], &g_k [(size_t)(b * T_ + k0 + r) * C_ + h * D_ + c4]);
        cpa16(&Vs[r * SVW + c4], &g_vt[((size_t)((b * H_ + h) * D_ + r)) * T_ + k0 + c4]);
    }
}

__global__ __launch_bounds__(128) void attn_mma_kernel()
{
    extern __shared__ uint32_t sm[];
    uint32_t* Ps = sm + 2 * AST_W;

    const int tid  = threadIdx.x;
    const int lane = tid & 31;
    const int warp = tid >> 5;
    const int lg   = lane >> 2;
    const int lt   = lane & 3;
    const int h    = blockIdx.y;
    const int b    = blockIdx.z;
    const int qbase = (gridDim.x - 1 - blockIdx.x) * 128;   // heavy-first

    const float LOG2E = 1.4426950408889634f;
    const float scale = 0.125f * LOG2E;
    const float slope = exp2f(-0.5f * (float)(h + 1)) * LOG2E;

    const int arow = (lane & 7) + ((lane >> 3) & 1) * 8;
    const int acol = ((lane >> 4) & 1) * 4;
    const int brw  = (lane & 7) + ((lane >> 4) & 1) * 8;
    const int bcl  = ((lane >> 3) & 1) * 4;
    const uint32_t sm_u32 = (uint32_t)__cvta_generic_to_shared(sm);
    const uint32_t ps_u32 = sm_u32 + (uint32_t)(2 * AST_W) * 4u
                          + (uint32_t)(warp * 32 * SPW) * 4u;

    const int wmin = qbase + warp * 32;
    const int r00 = wmin + lg;
    const int r10 = wmin + 16 + lg;

    uint32_t qf[2][8][4];
    {
        const float* qa = &g_q[((size_t)(b * T_ + r00)) * C_ + h * D_];
        const float* qb = &g_q[((size_t)(b * T_ + r00 + 8)) * C_ + h * D_];
        const float* qc = &g_q[((size_t)(b * T_ + r10)) * C_ + h * D_];
        const float* qd = &g_q[((size_t)(b * T_ + r10 + 8)) * C_ + h * D_];
        #pragma unroll
        for (int ks = 0; ks < 8; ks++) {
            int c = ks * 8 + lt;
            qf[0][ks][0] = f2tf32(qa[c] * scale);
            qf[0][ks][1] = f2tf32(qb[c] * scale);
            qf[0][ks][2] = f2tf32(qa[c + 4] * scale);
            qf[0][ks][3] = f2tf32(qb[c + 4] * scale);
            qf[1][ks][0] = f2tf32(qc[c] * scale);
            qf[1][ks][1] = f2tf32(qd[c] * scale);
            qf[1][ks][2] = f2tf32(qc[c + 4] * scale);
            qf[1][ks][3] = f2tf32(qd[c + 4] * scale);
        }
    }

    float oacc[2][8][4];
    #pragma unroll
    for (int mg = 0; mg < 2; mg++)
        #pragma unroll
        for (int nf = 0; nf < 8; nf++)
            #pragma unroll
            for (int r = 0; r < 4; r++) oacc[mg][nf][r] = 0.f;
    float mrow[2][2] = { {-1e30f, -1e30f}, {-1e30f, -1e30f} };
    float lrow[2][2] = { {0.f, 0.f}, {0.f, 0.f} };

    const int ntiles = qbase / AKT + 2;
    uint32_t* Pw = Ps + warp * 32 * SPW;

    attn_issue_kv(sm, b, h, 0, tid); CP_COMMIT();

    #pragma unroll 1
    for (int t = 0; t < ntiles; t++) {
        CP_WAIT(0);
        __syncthreads();
        if (t + 1 < ntiles)
            attn_issue_kv(sm + ((t + 1) & 1) * AST_W, b, h, (t + 1) * AKT, tid);
        CP_COMMIT();

        const int k0 = t * AKT;
        if (k0 > wmin + 31) continue;   // tile fully masked for this warp

        const uint32_t ks_u32 = sm_u32 + (uint32_t)((t & 1) * AST_W) * 4u;
        const uint32_t vs_u32 = ks_u32 + (uint32_t)(AKT * SKW) * 4u;
        const uint32_t kb_base = ks_u32 + (uint32_t)(brw * SKW + bcl) * 4u;
        const uint32_t vb_base = vs_u32 + (uint32_t)(brw * SVW + bcl) * 4u;

        // S = Q K^T
        float s[2][8][4];
        #pragma unroll
        for (int mg = 0; mg < 2; mg++)
            #pragma unroll
            for (int nf = 0; nf < 8; nf++)
                #pragma unroll
                for (int r = 0; r < 4; r++) s[mg][nf][r] = 0.f;

        #pragma unroll
        for (int ks = 0; ks < 8; ks++) {
            int kb = ks * 8;
            uint32_t bk[4][4];
            #pragma unroll
            for (int p = 0; p < 4; p++)
                ldsm4(bk[p], kb_base + (uint32_t)(p * 16 * SKW + kb) * 4u);
            #pragma unroll
            for (int mg = 0; mg < 2; mg++)
                #pragma unroll
                for (int p = 0; p < 4; p++) {
                    mma_tf32(s[mg][2*p],   qf[mg][ks][0], qf[mg][ks][1], qf[mg][ks][2], qf[mg][ks][3], bk[p][0], bk[p][1]);
                    mma_tf32(s[mg][2*p+1], qf[mg][ks][0], qf[mg][ks][1], qf[mg][ks][2], qf[mg][ks][3], bk[p][2], bk[p][3]);
                }
        }

        // ALiBi + causal + row max
        float rmax[2][2] = { {-1e30f, -1e30f}, {-1e30f, -1e30f} };
        if (k0 + AKT - 1 <= wmin) {
            #pragma unroll
            for (int mg = 0; mg < 2; mg++) {
                int ra = mg ? r10 : r00;
                #pragma unroll
                for (int nf = 0; nf < 8; nf++) {
                    int kj = k0 + nf * 8 + 2 * lt;
                    s[mg][nf][0] += slope * (float)(kj - ra);
                    s[mg][nf][1] += slope * (float)(kj + 1 - ra);
                    s[mg][nf][2] += slope * (float)(kj - (ra + 8));
                    s[mg][nf][3] += slope * (float)(kj + 1 - (ra + 8));
                    rmax[mg][0] = fmaxf(rmax[mg][0], fmaxf(s[mg][nf][0], s[mg][nf][1]));
                    rmax[mg][1] = fmaxf(rmax[mg][1], fmaxf(s[mg][nf][2], s[mg][nf][3]));
                }
            }
        } else {
            #pragma unroll
            for (int mg = 0; mg < 2; mg++) {
                int ra = mg ? r10 : r00;
                #pragma unroll
                for (int nf = 0; nf < 8; nf++) {
                    int kj = k0 + nf * 8 + 2 * lt;
                    int d00 = kj - ra, d01 = kj + 1 - ra;
                    int d10 = kj - (ra + 8), d11 = kj + 1 - (ra + 8);
                    s[mg][nf][0] = (d00 <= 0) ? s[mg][nf][0] + slope * (float)d00 : -1e30f;
                    s[mg][nf][1] = (d01 <= 0) ? s[mg][nf][1] + slope * (float)d01 : -1e30f;
                    s[mg][nf][2] = (d10 <= 0) ? s[mg][nf][2] + slope * (float)d10 : -1e30f;
                    s[mg][nf][3] = (d11 <= 0) ? s[mg][nf][3] + slope * (float)d11 : -1e30f;
                    rmax[mg][0] = fmaxf(rmax[mg][0], fmaxf(s[mg][nf][0], s[mg][nf][1]));
                    rmax[mg][1] = fmaxf(rmax[mg][1], fmaxf(s[mg][nf][2], s[mg][nf][3]));
                }
            }
        }
        #pragma unroll
        for (int mg = 0; mg < 2; mg++)
            #pragma unroll
            for (int hh = 0; hh < 2; hh++) {
                float v = rmax[mg][hh];
                v = fmaxf(v, __shfl_xor_sync(0xffffffffu, v, 1));
                v = fmaxf(v, __shfl_xor_sync(0xffffffffu, v, 2));
                rmax[mg][hh] = v;
            }

        float corr[2][2], mn[2][2];
        #pragma unroll
        for (int mg = 0; mg < 2; mg++)
            #pragma unroll
            for (int hh = 0; hh < 2; hh++) {
                mn[mg][hh] = fmaxf(mrow[mg][hh], rmax[mg][hh]);
                corr[mg][hh] = ex2f(mrow[mg][hh] - mn[mg][hh]);
                lrow[mg][hh] *= corr[mg][hh];
                mrow[mg][hh] = mn[mg][hh];
            }

        // P = exp2(S - m) -> SMEM (tf32), row sums
        float rs[2][2] = { {0.f, 0.f}, {0.f, 0.f} };
        #pragma unroll
        for (int mg = 0; mg < 2; mg++) {
            int row0 = mg * 16 + lg;
            #pragma unroll
            for (int nf = 0; nf < 8; nf++) {
                float p0 = ex2f(s[mg][nf][0] - mn[mg][0]);
                float p1 = ex2f(s[mg][nf][1] - mn[mg][0]);
                float p2 = ex2f(s[mg][nf][2] - mn[mg][1]);
                float p3 = ex2f(s[mg][nf][3] - mn[mg][1]);
                rs[mg][0] += p0 + p1;
                rs[mg][1] += p2 + p3;
                uint32_t* pr = &Pw[row0 * SPW + nf * 8 + 2 * lt];
                uint2 u0 = { f2tf32(p0), f2tf32(p1) };
                uint2 u1 = { f2tf32(p2), f2tf32(p3) };
                *(uint2*)pr = u0;
                *(uint2*)(pr + 8 * SPW) = u1;
            }
        }
        #pragma unroll
        for (int mg = 0; mg < 2; mg++)
            #pragma unroll
            for (int hh = 0; hh < 2; hh++) {
                float v = rs[mg][hh];
                v += __shfl_xor_sync(0xffffffffu, v, 1);
                v += __shfl_xor_sync(0xffffffffu, v, 2);
                lrow[mg][hh] += v;
            }

        #pragma unroll
        for (int mg = 0; mg < 2; mg++)
            #pragma unroll
            for (int nf = 0; nf < 8; nf++) {
                oacc[mg][nf][0] *= corr[mg][0];
                oacc[mg][nf][1] *= corr[mg][0];
                oacc[mg][nf][2] *= corr[mg][1];
                oacc[mg][nf][3] *= corr[mg][1];
            }

        __syncwarp();

        // O += P V : A-frags from P (ldmatrix), B-frags from VsT (ldmatrix)
        const uint32_t pa_base = ps_u32 + (uint32_t)(arow * SPW + acol) * 4u;
        #pragma unroll
        for (int ks = 0; ks < 8; ks++) {
            int kb = ks * 8;
            uint32_t bv[4][4];
            #pragma unroll
            for (int p = 0; p < 4; p++)
                ldsm4(bv[p], vb_base + (uint32_t)(p * 16 * SVW + kb) * 4u);
            #pragma unroll
            for (int mg = 0; mg < 2; mg++) {
                uint32_t a[4];
                ldsm4(a, pa_base + (uint32_t)(mg * 16 * SPW + kb) * 4u);
                #pragma unroll
                for (int p = 0; p < 4; p++) {
                    mma_tf32(oacc[mg][2*p],   a[0], a[1], a[2], a[3], bv[p][0], bv[p][1]);
                    mma_tf32(oacc[mg][2*p+1], a[0], a[1], a[2], a[3], bv[p][2], bv[p][3]);
                }
            }
        }
    }

    // Final normalize + tf32-rounded store (g_o feeds tf32 out-proj GEMM).
    #pragma unroll
    for (int mg = 0; mg < 2; mg++) {
        int ra = mg ? r10 : r00;
        float inv0 = 1.f / lrow[mg][0], inv1 = 1.f / lrow[mg][1];
        float* o0 = &g_o[((size_t)(b * T_ + ra)) * C_ + h * D_];
        float* o1 = &g_o[((size_t)(b * T_ + ra + 8)) * C_ + h * D_];
        #pragma unroll
        for (int nf = 0; nf < 8; nf++) {
            int c = nf * 8 + 2 * lt;
            uint2 v0 = { f2tf32(oacc[mg][nf][0] * inv0), f2tf32(oacc[mg][nf][1] * inv0) };
            uint2 v1 = { f2tf32(oacc[mg][nf][2] * inv1), f2tf32(oacc[mg][nf][3] * inv1) };
            *(uint2*)&o0[c] = v0;
            *(uint2*)&o1[c] = v1;
        }
    }
}

// ---------------------------------------------------------------------------
extern "C" void kernel_launch(void* const* d_in, const int* in_sizes, int n_in,
                              void* d_out, int out_size)
{
    const float* x  = (const float*)d_in[0];
    const float* Wq = (const float*)d_in[1];
    const float* bq = (const float*)d_in[2];
    const float* Wk = (const float*)d_in[3];
    const float* bk = (const float*)d_in[4];
    const float* Wv = (const float*)d_in[5];
    const float* bv = (const float*)d_in[6];
    const float* Wo = (const float*)d_in[7];
    const float* bo = (const float*)d_in[8];
    float* out = (float*)d_out;

    cudaFuncSetAttribute(qkv_gemm_kernel,
                         cudaFuncAttributeMaxDynamicSharedMemorySize, GEMM_SMEM);
    cudaFuncSetAttribute(out_gemm_kernel,
                         cudaFuncAttributeMaxDynamicSharedMemorySize, GEMM_SMEM);
    cudaFuncSetAttribute(attn_mma_kernel,
                         cudaFuncAttributeMaxDynamicSharedMemorySize, ATT_SMEM);

    conv_x_kernel<<<1024, 256>>>(x);
    conv_w_kernel<<<1024, 256>>>(Wq, Wk, Wv, Wo);

    qkv_gemm_kernel<<<dim3(24, 32), 256, GEMM_SMEM>>>(bq, bk, bv);

    vt_kernel<<<dim3(T_ / 64, H_, B_), 256>>>();

    attn_mma_kernel<<<dim3(T_ / 128, H_, B_), 128, ATT_SMEM>>>();

    out_gemm_kernel<<<dim3(8, 32), 256, GEMM_SMEM>>>(bo, out);
}

// round 9
// speedup vs baseline: 8.3688x; 1.7600x over previous
#include <cuda_runtime.h>
#include <cuda_fp16.h>
#include <stdint.h>
#include <math.h>

#define B_ 2
#define T_ 2048
#define C_ 1024
#define H_ 16
#define D_ 64
#define M_ (B_*T_)   // 4096 rows

// Scratch (allocation-free). All half except where noted.
__device__ __half g_qh[M_*C_];     // Q, pre-scaled by 0.125*log2e
__device__ __half g_kh[M_*C_];
__device__ __half g_vh[M_*C_];
__device__ __half g_vth[M_*C_];    // V transposed: [b][h][d][t]
__device__ __half g_oh[M_*C_];     // attention out
__device__ __half g_xh[M_*C_];     // x rounded to fp16
__device__ __half g_wh[4*C_*C_];   // W^T rounded to fp16: [sel][n][k]

__device__ __forceinline__ float ex2f(float x) {
    float y;
    asm("ex2.approx.ftz.f32 %0, %1;" : "=f"(y) : "f"(x));
    return y;
}

__device__ __forceinline__ void mma_f16(float c[4],
    uint32_t a0, uint32_t a1, uint32_t a2, uint32_t a3,
    uint32_t b0, uint32_t b1)
{
    asm volatile(
        "mma.sync.aligned.m16n8k16.row.col.f32.f16.f16.f32 "
        "{%0,%1,%2,%3},{%4,%5,%6,%7},{%8,%9},{%0,%1,%2,%3};"
        : "+f"(c[0]), "+f"(c[1]), "+f"(c[2]), "+f"(c[3])
        : "r"(a0), "r"(a1), "r"(a2), "r"(a3), "r"(b0), "r"(b1));
}

__device__ __forceinline__ void ldsm4(uint32_t r[4], uint32_t saddr) {
    asm volatile("ldmatrix.sync.aligned.m8n8.x4.shared.b16 {%0,%1,%2,%3}, [%4];"
        : "=r"(r[0]), "=r"(r[1]), "=r"(r[2]), "=r"(r[3]) : "r"(saddr));
}

__device__ __forceinline__ void cpa16(void* dst, const void* src) {
    uint32_t d = (uint32_t)__cvta_generic_to_shared(dst);
    asm volatile("cp.async.cg.shared.global [%0], [%1], 16;" :: "r"(d), "l"(src));
}
#define CP_COMMIT() asm volatile("cp.async.commit_group;")
#define CP_WAIT(N)  asm volatile("cp.async.wait_group %0;" :: "n"(N))

__device__ __forceinline__ uint32_t pack_h2(float a, float b) {
    __half2 h = __floats2half2_rn(a, b);
    return *(uint32_t*)&h;
}

// ---------------------------------------------------------------------------
// conv_x: x fp32 -> g_xh fp16. 1M float4; grid 1024 x 256thr x 4.
// ---------------------------------------------------------------------------
__global__ __launch_bounds__(256) void conv_x_kernel(const float* __restrict__ x)
{
    #pragma unroll
    for (int l = 0; l < 4; l++) {
        int i4 = blockIdx.x * 1024 + l * 256 + threadIdx.x;
        float4 v = *(const float4*)&x[(size_t)i4 << 2];
        uint2 u = { pack_h2(v.x, v.y), pack_h2(v.z, v.w) };
        *(uint2*)&g_xh[(size_t)i4 << 2] = u;
    }
}

// ---------------------------------------------------------------------------
// conv_w: fp32 W[k][n] -> fp16 W^T[n][k]. 64x64 tiles; grid 4*256.
// ---------------------------------------------------------------------------
__global__ __launch_bounds__(256) void conv_w_kernel(
    const float* __restrict__ Wq, const float* __restrict__ Wk,
    const float* __restrict__ Wv, const float* __restrict__ Wo)
{
    __shared__ __half tile[64][68];
    const float* Ws[4] = { Wq, Wk, Wv, Wo };
    int mat = blockIdx.x >> 8;
    int t   = blockIdx.x & 255;
    int kb  = (t >> 4) << 6;
    int nb  = (t & 15) << 6;
    const float* W = Ws[mat];
    int tid = threadIdx.x;
    int rr = tid >> 4, c4 = (tid & 15) << 2;
    #pragma unroll
    for (int l = 0; l < 4; l++) {
        int row = rr + l * 16;   // k row
        float4 v = *(const float4*)&W[(size_t)(kb + row) * C_ + nb + c4];
        tile[row][c4 + 0] = __float2half_rn(v.x);
        tile[row][c4 + 1] = __float2half_rn(v.y);
        tile[row][c4 + 2] = __float2half_rn(v.z);
        tile[row][c4 + 3] = __float2half_rn(v.w);
    }
    __syncthreads();
    __half* dst = g_wh + ((size_t)mat << 20);
    #pragma unroll
    for (int l = 0; l < 4; l++) {
        int row = rr + l * 16;   // n row
        __half2 p0 = __halves2half2(tile[c4 + 0][row], tile[c4 + 1][row]);
        __half2 p1 = __halves2half2(tile[c4 + 2][row], tile[c4 + 3][row]);
        uint2 u = { *(uint32_t*)&p0, *(uint32_t*)&p1 };
        *(uint2*)&dst[(size_t)(nb + row) * C_ + kb + c4] = u;
    }
}

// ---------------------------------------------------------------------------
// vt: transpose V (half) per (b,h): g_vth[((b*H+h)*D+d)*T+t] = g_vh[(b*T+t)*C+h*D+d]
// ---------------------------------------------------------------------------
__global__ __launch_bounds__(256) void vt_kernel()
{
    __shared__ __half tile[64][68];
    int t0 = blockIdx.x * 64;
    int h  = blockIdx.y;
    int b  = blockIdx.z;
    int tid = threadIdx.x;
    int rr = tid >> 4, c4 = (tid & 15) << 2;
    #pragma unroll
    for (int l = 0; l < 4; l++) {
        int row = rr + l * 16;   // t offset
        uint2 v = *(const uint2*)&g_vh[(size_t)(b * T_ + t0 + row) * C_ + h * D_ + c4];
        *(uint2*)&tile[row][c4] = v;
    }
    __syncthreads();
    #pragma unroll
    for (int l = 0; l < 4; l++) {
        int row = rr + l * 16;   // d index
        __half2 p0 = __halves2half2(tile[c4 + 0][row], tile[c4 + 1][row]);
        __half2 p1 = __halves2half2(tile[c4 + 2][row], tile[c4 + 3][row]);
        uint2 u = { *(uint32_t*)&p0, *(uint32_t*)&p1 };
        *(uint2*)&g_vth[((size_t)((b * H_ + h) * D_ + row)) * T_ + t0 + c4] = u;
    }
}

// ---------------------------------------------------------------------------
// FP16 GEMM (m16n8k16): C[M,N] = A[M,K] @ W[K,N] + bias.
// A [m][k] half, Wt [n][k] half. 128x128 tile, BK=64, 3-stage cp.async,
// 256 thr (8 warps 2x4), warp 64x32. ldmatrix fragments.
// ---------------------------------------------------------------------------
#define SAH 72                      // stride in halves (144B, conflict-free)
#define STG_H (256*SAH)             // 18432 halves per stage
#define GEMM_SMEM (3*STG_H*2)       // 110592 bytes

__device__ __forceinline__ void gemm_issue(
    __half* stage, const __half* A, const __half* Wt,
    int brow, int bcol, int k0, int tid)
{
    __half* As = stage;
    __half* Ws = stage + 128 * SAH;
    #pragma unroll
    for (int l = 0; l < 8; l++) {
        int idx = tid + (l << 8);
        int row = idx >> 3;
        int c16 = (idx & 7) << 3;
        if (row < 128)
            cpa16(&As[row * SAH + c16], &A[(size_t)(brow + row) * C_ + k0 + c16]);
        else
            cpa16(&Ws[(row - 128) * SAH + c16],
                  &Wt[(size_t)(bcol + row - 128) * C_ + k0 + c16]);
    }
}

__device__ __forceinline__ void gemm_pipe(
    const __half* __restrict__ A, const __half* __restrict__ Wt,
    const float* __restrict__ bias, void* __restrict__ Cm,
    int brow, int bcol, int outHalf, float sc)
{
    extern __shared__ __half smh[];
    const int tid  = threadIdx.x;
    const int lane = tid & 31;
    const int warp = tid >> 5;
    const int wr   = warp >> 2;
    const int wc   = warp & 3;
    const int lg   = lane >> 2;
    const int lt   = lane & 3;

    // ldmatrix thread source offsets
    const int arow = lane & 15;                // A/P matrices: m-lo/k-lo, m-hi/k-lo, m-lo/k-hi, m-hi/k-hi
    const int ah8  = ((lane >> 4) & 1) * 8;
    const int brw  = ((lane >> 4) & 1) * 8 + (lane & 7);  // B: n-lo/k-lo, n-lo/k-hi, n-hi/k-lo, n-hi/k-hi
    const int bh8  = ((lane >> 3) & 1) * 8;
    const uint32_t smem_u32 = (uint32_t)__cvta_generic_to_shared(smh);

    float acc[4][4][4];
    #pragma unroll
    for (int mf = 0; mf < 4; mf++)
        #pragma unroll
        for (int nf = 0; nf < 4; nf++)
            #pragma unroll
            for (int r = 0; r < 4; r++) acc[mf][nf][r] = 0.f;

    gemm_issue(smh,             A, Wt, brow, bcol, 0,  tid); CP_COMMIT();
    gemm_issue(smh + STG_H,     A, Wt, brow, bcol, 64, tid); CP_COMMIT();

    const int NIT = C_ / 64;   // 16
    #pragma unroll 1
    for (int it = 0; it < NIT; it++) {
        CP_WAIT(1);
        __syncthreads();
        int kn = (it + 2) * 64;
        if (kn < C_) gemm_issue(smh + ((it + 2) % 3) * STG_H, A, Wt, brow, bcol, kn, tid);
        CP_COMMIT();

        uint32_t sbase = smem_u32 + (uint32_t)((it % 3) * STG_H) * 2u;
        uint32_t aaddr = sbase + (uint32_t)((wr * 64 + arow) * SAH + ah8) * 2u;
        uint32_t baddr = sbase + (uint32_t)(128 * SAH) * 2u
                       + (uint32_t)((wc * 32 + brw) * SAH + bh8) * 2u;

        #pragma unroll
        for (int ks = 0; ks < 4; ks++) {
            const int kb = ks * 16;
            uint32_t b0[4], b1[4];
            ldsm4(b0, baddr + (uint32_t)kb * 2u);                   // n 0-15
            ldsm4(b1, baddr + (uint32_t)(16 * SAH + kb) * 2u);      // n 16-31
            #pragma unroll
            for (int mf = 0; mf < 4; mf++) {
                uint32_t a[4];
                ldsm4(a, aaddr + (uint32_t)(mf * 16 * SAH + kb) * 2u);
                mma_f16(acc[mf][0], a[0], a[1], a[2], a[3], b0[0], b0[1]);
                mma_f16(acc[mf][1], a[0], a[1], a[2], a[3], b0[2], b0[3]);
                mma_f16(acc[mf][2], a[0], a[1], a[2], a[3], b1[0], b1[1]);
                mma_f16(acc[mf][3], a[0], a[1], a[2], a[3], b1[2], b1[3]);
            }
        }
    }

    #pragma unroll
    for (int mf = 0; mf < 4; mf++) {
        int row0 = brow + wr * 64 + mf * 16 + lg;
        #pragma unroll
        for (int nf = 0; nf < 4; nf++) {
            int col = bcol + wc * 32 + nf * 8 + lt * 2;
            float bx = bias[col], by = bias[col + 1];
            float v00 = (acc[mf][nf][0] + bx) * sc, v01 = (acc[mf][nf][1] + by) * sc;
            float v10 = (acc[mf][nf][2] + bx) * sc, v11 = (acc[mf][nf][3] + by) * sc;
            if (outHalf) {
                __half* Ch = (__half*)Cm;
                uint32_t o0 = pack_h2(v00, v01), o1 = pack_h2(v10, v11);
                *(uint32_t*)&Ch[(size_t)row0 * C_ + col]       = o0;
                *(uint32_t*)&Ch[(size_t)(row0 + 8) * C_ + col] = o1;
            } else {
                float* Cf = (float*)Cm;
                float2 o0 = { v00, v01 };
                float2 o1 = { v10, v11 };
                *(float2*)&Cf[(size_t)row0 * C_ + col]       = o0;
                *(float2*)&Cf[(size_t)(row0 + 8) * C_ + col] = o1;
            }
        }
    }
}

__global__ __launch_bounds__(256) void qkv_gemm_kernel(
    const float* __restrict__ bq, const float* __restrict__ bk,
    const float* __restrict__ bv)
{
    int sel  = blockIdx.x >> 3;
    int bcol = (blockIdx.x & 7) * 128;
    int brow = blockIdx.y * 128;
    const __half* Wt  = g_wh + ((size_t)sel << 20);
    const float* bias = (sel == 0) ? bq : (sel == 1) ? bk : bv;
    __half* Cm        = (sel == 0) ? g_qh : (sel == 1) ? g_kh : g_vh;
    float sc = (sel == 0) ? 0.125f * 1.4426950408889634f : 1.0f;  // fold scale*log2e into Q
    gemm_pipe(g_xh, Wt, bias, Cm, brow, bcol, 1, sc);
}

__global__ __launch_bounds__(256) void out_gemm_kernel(
    const float* __restrict__ bo, float* __restrict__ out)
{
    gemm_pipe(g_oh, g_wh + ((size_t)3 << 20), bo, out,
              blockIdx.y * 128, blockIdx.x * 128, 0, 1.0f);
}

// ---------------------------------------------------------------------------
// FP16 flash attention (m16n8k16), ALiBi + causal.
// 128 thr (4 warps), warp owns 16 query rows, CTA 64 queries.
// 2-stage cp.async KV; dedicated P region. SMEM 46080B -> 4 CTA/SM.
// ---------------------------------------------------------------------------
#define SKH 72
#define AST_H (128*SKH)                  // 9216 halves per stage (K 64 rows + Vt 64 rows)
#define PS_HW (64*SKH)                   // 4608 halves
#define ATT_SMEM ((2*AST_H + PS_HW)*2)   // 46080 bytes

__device__ __forceinline__ void attn_issue_kv(
    __half* stage, int b, int h, int k0, int tid)
{
    __half* Ks = stage;
    __half* Vs = stage + 64 * SKH;
    #pragma unroll
    for (int l = 0; l < 8; l++) {
        int idx = tid + (l << 7);
        int row = idx >> 3;
        int c16 = (idx & 7) << 3;
        if (row < 64)
            cpa16(&Ks[row * SKH + c16],
                  &g_kh[(size_t)(b * T_ + k0 + row) * C_ + h * D_ + c16]);
        else
            cpa16(&Vs[(row - 64) * SKH + c16],
                  &g_vth[((size_t)((b * H_ + h) * D_ + row - 64)) * T_ + k0 + c16]);
    }
}

__global__ __launch_bounds__(128) void attn_mma_kernel()
{
    extern __shared__ __half smh[];
    __half* Ps = smh + 2 * AST_H;

    const int tid  = threadIdx.x;
    const int lane = tid & 31;
    const int warp = tid >> 5;
    const int lg   = lane >> 2;
    const int lt   = lane & 3;
    const int h    = blockIdx.y;
    const int b    = blockIdx.z;
    const int qbase = (gridDim.x - 1 - blockIdx.x) * 64;   // heavy-first

    const float LOG2E = 1.4426950408889634f;
    const float slope = exp2f(-0.5f * (float)(h + 1)) * LOG2E;

    const int arow = lane & 15;
    const int ah8  = ((lane >> 4) & 1) * 8;
    const int brw  = ((lane >> 4) & 1) * 8 + (lane & 7);
    const int bh8  = ((lane >> 3) & 1) * 8;
    const uint32_t sm_u32 = (uint32_t)__cvta_generic_to_shared(smh);
    const uint32_t ps_u32 = sm_u32 + (uint32_t)(2 * AST_H) * 2u;

    const int wmin = qbase + warp * 16;
    const int r0 = wmin + lg;

    // Q fragments (Q pre-scaled). a0=Q[r0][kb+2lt..], a1=row+8, a2=+8 halves, a3=both.
    uint32_t qf[4][4];
    {
        const __half* q0 = &g_qh[(size_t)(b * T_ + r0) * C_ + h * D_];
        const __half* q1 = q0 + 8 * C_;
        #pragma unroll
        for (int ks = 0; ks < 4; ks++) {
            int c = ks * 16 + 2 * lt;
            qf[ks][0] = *(const uint32_t*)&q0[c];
            qf[ks][1] = *(const uint32_t*)&q1[c];
            qf[ks][2] = *(const uint32_t*)&q0[c + 8];
            qf[ks][3] = *(const uint32_t*)&q1[c + 8];
        }
    }

    float oacc[8][4];
    #pragma unroll
    for (int nf = 0; nf < 8; nf++)
        #pragma unroll
        for (int r = 0; r < 4; r++) oacc[nf][r] = 0.f;
    float m0 = -1e30f, m1 = -1e30f, l0 = 0.f, l1 = 0.f;

    const int ntiles = qbase / 64 + 1;
    __half* Pw = Ps + warp * 16 * SKH;
    const uint32_t pw_u32 = ps_u32 + (uint32_t)(warp * 16 * SKH) * 2u;

    attn_issue_kv(smh, b, h, 0, tid); CP_COMMIT();

    #pragma unroll 1
    for (int t = 0; t < ntiles; t++) {
        CP_WAIT(0);
        __syncthreads();
        if (t + 1 < ntiles)
            attn_issue_kv(smh + ((t + 1) & 1) * AST_H, b, h, (t + 1) * 64, tid);
        CP_COMMIT();

        const int k0 = t * 64;
        if (k0 > wmin + 15) continue;   // fully masked for this warp

        const uint32_t st_u32 = sm_u32 + (uint32_t)((t & 1) * AST_H) * 2u;
        const uint32_t kaddr  = st_u32 + (uint32_t)(brw * SKH + bh8) * 2u;
        const uint32_t vaddr  = st_u32 + (uint32_t)(64 * SKH) * 2u
                              + (uint32_t)(brw * SKH + bh8) * 2u;

        // S = Q K^T  (16 x 64)
        float s[8][4];
        #pragma unroll
        for (int nf = 0; nf < 8; nf++)
            #pragma unroll
            for (int r = 0; r < 4; r++) s[nf][r] = 0.f;

        #pragma unroll
        for (int ks = 0; ks < 4; ks++) {
            int kb = ks * 16;
            #pragma unroll
            for (int p = 0; p < 4; p++) {
                uint32_t bk[4];
                ldsm4(bk, kaddr + (uint32_t)(p * 16 * SKH + kb) * 2u);
                mma_f16(s[2*p],   qf[ks][0], qf[ks][1], qf[ks][2], qf[ks][3], bk[0], bk[1]);
                mma_f16(s[2*p+1], qf[ks][0], qf[ks][1], qf[ks][2], qf[ks][3], bk[2], bk[3]);
            }
        }

        // ALiBi + causal + row max
        float rmax0 = -1e30f, rmax1 = -1e30f;
        if (k0 + 63 <= wmin) {
            #pragma unroll
            for (int nf = 0; nf < 8; nf++) {
                int kj = k0 + nf * 8 + 2 * lt;
                s[nf][0] += slope * (float)(kj - r0);
                s[nf][1] += slope * (float)(kj + 1 - r0);
                s[nf][2] += slope * (float)(kj - (r0 + 8));
                s[nf][3] += slope * (float)(kj + 1 - (r0 + 8));
                rmax0 = fmaxf(rmax0, fmaxf(s[nf][0], s[nf][1]));
                rmax1 = fmaxf(rmax1, fmaxf(s[nf][2], s[nf][3]));
            }
        } else {
            #pragma unroll
            for (int nf = 0; nf < 8; nf++) {
                int kj = k0 + nf * 8 + 2 * lt;
                int d00 = kj - r0, d01 = kj + 1 - r0;
                int d10 = kj - (r0 + 8), d11 = kj + 1 - (r0 + 8);
                s[nf][0] = (d00 <= 0) ? s[nf][0] + slope * (float)d00 : -1e30f;
                s[nf][1] = (d01 <= 0) ? s[nf][1] + slope * (float)d01 : -1e30f;
                s[nf][2] = (d10 <= 0) ? s[nf][2] + slope * (float)d10 : -1e30f;
                s[nf][3] = (d11 <= 0) ? s[nf][3] + slope * (float)d11 : -1e30f;
                rmax0 = fmaxf(rmax0, fmaxf(s[nf][0], s[nf][1]));
                rmax1 = fmaxf(rmax1, fmaxf(s[nf][2], s[nf][3]));
            }
        }
        rmax0 = fmaxf(rmax0, __shfl_xor_sync(0xffffffffu, rmax0, 1));
        rmax0 = fmaxf(rmax0, __shfl_xor_sync(0xffffffffu, rmax0, 2));
        rmax1 = fmaxf(rmax1, __shfl_xor_sync(0xffffffffu, rmax1, 1));
        rmax1 = fmaxf(rmax1, __shfl_xor_sync(0xffffffffu, rmax1, 2));

        float mn0 = fmaxf(m0, rmax0), mn1 = fmaxf(m1, rmax1);
        float c0 = ex2f(m0 - mn0),  c1 = ex2f(m1 - mn1);
        l0 *= c0; l1 *= c1;
        m0 = mn0; m1 = mn1;

        // P = exp2(S - m) -> SMEM (fp16), row sums
        float rs0 = 0.f, rs1 = 0.f;
        #pragma unroll
        for (int nf = 0; nf < 8; nf++) {
            float p0 = ex2f(s[nf][0] - mn0);
            float p1 = ex2f(s[nf][1] - mn0);
            float p2 = ex2f(s[nf][2] - mn1);
            float p3 = ex2f(s[nf][3] - mn1);
            rs0 += p0 + p1;
            rs1 += p2 + p3;
            int c = nf * 8 + 2 * lt;
            *(uint32_t*)&Pw[lg * SKH + c]       = pack_h2(p0, p1);
            *(uint32_t*)&Pw[(lg + 8) * SKH + c] = pack_h2(p2, p3);
        }
        rs0 += __shfl_xor_sync(0xffffffffu, rs0, 1);
        rs0 += __shfl_xor_sync(0xffffffffu, rs0, 2);
        rs1 += __shfl_xor_sync(0xffffffffu, rs1, 1);
        rs1 += __shfl_xor_sync(0xffffffffu, rs1, 2);
        l0 += rs0; l1 += rs1;

        #pragma unroll
        for (int nf = 0; nf < 8; nf++) {
            oacc[nf][0] *= c0; oacc[nf][1] *= c0;
            oacc[nf][2] *= c1; oacc[nf][3] *= c1;
        }

        __syncwarp();

        // O += P V : A-frags from P, B-frags from Vt[dim][key] (both ldmatrix)
        const uint32_t paddr = pw_u32 + (uint32_t)(arow * SKH + ah8) * 2u;
        #pragma unroll
        for (int ks = 0; ks < 4; ks++) {
            int kb = ks * 16;
            uint32_t a[4];
            ldsm4(a, paddr + (uint32_t)kb * 2u);
            #pragma unroll
            for (int p = 0; p < 4; p++) {
                uint32_t bv[4];
                ldsm4(bv, vaddr + (uint32_t)(p * 16 * SKH + kb) * 2u);
                mma_f16(oacc[2*p],   a[0], a[1], a[2], a[3], bv[0], bv[1]);
                mma_f16(oacc[2*p+1], a[0], a[1], a[2], a[3], bv[2], bv[3]);
            }
        }
    }

    // Final normalize + fp16 store (g_oh feeds fp16 out-proj GEMM).
    float inv0 = 1.f / l0, inv1 = 1.f / l1;
    __half* o0 = &g_oh[(size_t)(b * T_ + r0) * C_ + h * D_];
    __half* o1 = o0 + 8 * C_;
    #pragma unroll
    for (int nf = 0; nf < 8; nf++) {
        int c = nf * 8 + 2 * lt;
        *(uint32_t*)&o0[c] = pack_h2(oacc[nf][0] * inv0, oacc[nf][1] * inv0);
        *(uint32_t*)&o1[c] = pack_h2(oacc[nf][2] * inv1, oacc[nf][3] * inv1);
    }
}

// ---------------------------------------------------------------------------
extern "C" void kernel_launch(void* const* d_in, const int* in_sizes, int n_in,
                              void* d_out, int out_size)
{
    const float* x  = (const float*)d_in[0];
    const float* Wq = (const float*)d_in[1];
    const float* bq = (const float*)d_in[2];
    const float* Wk = (const float*)d_in[3];
    const float* bk = (const float*)d_in[4];
    const float* Wv = (const float*)d_in[5];
    const float* bv = (const float*)d_in[6];
    const float* Wo = (const float*)d_in[7];
    const float* bo = (const float*)d_in[8];
    float* out = (float*)d_out;

    cudaFuncSetAttribute(qkv_gemm_kernel,
                         cudaFuncAttributeMaxDynamicSharedMemorySize, GEMM_SMEM);
    cudaFuncSetAttribute(out_gemm_kernel,
                         cudaFuncAttributeMaxDynamicSharedMemorySize, GEMM_SMEM);
    cudaFuncSetAttribute(attn_mma_kernel,
                         cudaFuncAttributeMaxDynamicSharedMemorySize, ATT_SMEM);

    conv_x_kernel<<<1024, 256>>>(x);
    conv_w_kernel<<<1024, 256>>>(Wq, Wk, Wv, Wo);

    qkv_gemm_kernel<<<dim3(24, 32), 256, GEMM_SMEM>>>(bq, bk, bv);

    vt_kernel<<<dim3(T_ / 64, H_, B_), 256>>>();

    attn_mma_kernel<<<dim3(T_ / 64, H_, B_), 128, ATT_SMEM>>>();

    out_gemm_kernel<<<dim3(8, 32), 256, GEMM_SMEM>>>(bo, out);
}

// round 10
// speedup vs baseline: 8.8801x; 1.0611x over previous
#include <cuda_runtime.h>
#include <cuda_fp16.h>
#include <stdint.h>
#include <math.h>

#define B_ 2
#define T_ 2048
#define C_ 1024
#define H_ 16
#define D_ 64
#define M_ (B_*T_)   // 4096 rows

// Scratch (allocation-free).
__device__ __half g_qh[M_*C_];     // Q, pre-scaled by 0.125*log2e
__device__ __half g_kh[M_*C_];
__device__ __half g_vh[M_*C_];
__device__ __half g_oh[M_*C_];     // attention out
__device__ __half g_xh[M_*C_];     // x rounded to fp16
__device__ __half g_wh[4*C_*C_];   // W^T rounded to fp16: [sel][n][k]

__device__ __forceinline__ float ex2f(float x) {
    float y;
    asm("ex2.approx.ftz.f32 %0, %1;" : "=f"(y) : "f"(x));
    return y;
}

__device__ __forceinline__ void mma_f16(float c[4],
    uint32_t a0, uint32_t a1, uint32_t a2, uint32_t a3,
    uint32_t b0, uint32_t b1)
{
    asm volatile(
        "mma.sync.aligned.m16n8k16.row.col.f32.f16.f16.f32 "
        "{%0,%1,%2,%3},{%4,%5,%6,%7},{%8,%9},{%0,%1,%2,%3};"
        : "+f"(c[0]), "+f"(c[1]), "+f"(c[2]), "+f"(c[3])
        : "r"(a0), "r"(a1), "r"(a2), "r"(a3), "r"(b0), "r"(b1));
}

__device__ __forceinline__ void ldsm4(uint32_t r[4], uint32_t saddr) {
    asm volatile("ldmatrix.sync.aligned.m8n8.x4.shared.b16 {%0,%1,%2,%3}, [%4];"
        : "=r"(r[0]), "=r"(r[1]), "=r"(r[2]), "=r"(r[3]) : "r"(saddr));
}

__device__ __forceinline__ void ldsm4t(uint32_t r[4], uint32_t saddr) {
    asm volatile("ldmatrix.sync.aligned.m8n8.x4.trans.shared.b16 {%0,%1,%2,%3}, [%4];"
        : "=r"(r[0]), "=r"(r[1]), "=r"(r[2]), "=r"(r[3]) : "r"(saddr));
}

__device__ __forceinline__ void cpa16(void* dst, const void* src) {
    uint32_t d = (uint32_t)__cvta_generic_to_shared(dst);
    asm volatile("cp.async.cg.shared.global [%0], [%1], 16;" :: "r"(d), "l"(src));
}
#define CP_COMMIT() asm volatile("cp.async.commit_group;")
#define CP_WAIT(N)  asm volatile("cp.async.wait_group %0;" :: "n"(N))

__device__ __forceinline__ uint32_t pack_h2(float a, float b) {
    __half2 h = __floats2half2_rn(a, b);
    return *(uint32_t*)&h;
}

// ---------------------------------------------------------------------------
// Fused conversion: blocks [0,1024) convert x fp32->fp16;
// blocks [1024,2048) round + transpose the 4 weight matrices (64x64 tiles).
// ---------------------------------------------------------------------------
__global__ __launch_bounds__(256) void conv_all_kernel(
    const float* __restrict__ x,
    const float* __restrict__ Wq, const float* __restrict__ Wk,
    const float* __restrict__ Wv, const float* __restrict__ Wo)
{
    __shared__ __half tile[64][68];
    if (blockIdx.x < 1024) {
        #pragma unroll
        for (int l = 0; l < 4; l++) {
            int i4 = blockIdx.x * 1024 + l * 256 + threadIdx.x;
            float4 v = *(const float4*)&x[(size_t)i4 << 2];
            uint2 u = { pack_h2(v.x, v.y), pack_h2(v.z, v.w) };
            *(uint2*)&g_xh[(size_t)i4 << 2] = u;
        }
        return;
    }
    const float* Ws[4] = { Wq, Wk, Wv, Wo };
    int bx  = blockIdx.x - 1024;
    int mat = bx >> 8;
    int t   = bx & 255;
    int kb  = (t >> 4) << 6;
    int nb  = (t & 15) << 6;
    const float* W = Ws[mat];
    int tid = threadIdx.x;
    int rr = tid >> 4, c4 = (tid & 15) << 2;
    #pragma unroll
    for (int l = 0; l < 4; l++) {
        int row = rr + l * 16;   // k row
        float4 v = *(const float4*)&W[(size_t)(kb + row) * C_ + nb + c4];
        tile[row][c4 + 0] = __float2half_rn(v.x);
        tile[row][c4 + 1] = __float2half_rn(v.y);
        tile[row][c4 + 2] = __float2half_rn(v.z);
        tile[row][c4 + 3] = __float2half_rn(v.w);
    }
    __syncthreads();
    __half* dst = g_wh + ((size_t)mat << 20);
    #pragma unroll
    for (int l = 0; l < 4; l++) {
        int row = rr + l * 16;   // n row
        __half2 p0 = __halves2half2(tile[c4 + 0][row], tile[c4 + 1][row]);
        __half2 p1 = __halves2half2(tile[c4 + 2][row], tile[c4 + 3][row]);
        uint2 u = { *(uint32_t*)&p0, *(uint32_t*)&p1 };
        *(uint2*)&dst[(size_t)(nb + row) * C_ + kb + c4] = u;
    }
}

// ---------------------------------------------------------------------------
// FP16 GEMM (m16n8k16): C[M,N] = A[M,K] @ W[K,N] + bias.
// A [m][k] half, Wt [n][k] half. 128x128 tile, BK=64, 3-stage cp.async,
// 256 thr (8 warps 2x4), warp 64x32. ldmatrix fragments.
// ---------------------------------------------------------------------------
#define SAH 72                      // stride in halves (144B, conflict-free)
#define STG_H (256*SAH)             // 18432 halves per stage
#define GEMM_SMEM (3*STG_H*2)       // 110592 bytes

__device__ __forceinline__ void gemm_issue(
    __half* stage, const __half* A, const __half* Wt,
    int brow, int bcol, int k0, int tid)
{
    __half* As = stage;
    __half* Ws = stage + 128 * SAH;
    #pragma unroll
    for (int l = 0; l < 8; l++) {
        int idx = tid + (l << 8);
        int row = idx >> 3;
        int c16 = (idx & 7) << 3;
        if (row < 128)
            cpa16(&As[row * SAH + c16], &A[(size_t)(brow + row) * C_ + k0 + c16]);
        else
            cpa16(&Ws[(row - 128) * SAH + c16],
                  &Wt[(size_t)(bcol + row - 128) * C_ + k0 + c16]);
    }
}

__device__ __forceinline__ void gemm_pipe(
    const __half* __restrict__ A, const __half* __restrict__ Wt,
    const float* __restrict__ bias, void* __restrict__ Cm,
    int brow, int bcol, int outHalf, float sc)
{
    extern __shared__ __half smh[];
    const int tid  = threadIdx.x;
    const int lane = tid & 31;
    const int warp = tid >> 5;
    const int wr   = warp >> 2;
    const int wc   = warp & 3;
    const int lg   = lane >> 2;
    const int lt   = lane & 3;

    const int arow = lane & 15;
    const int ah8  = ((lane >> 4) & 1) * 8;
    const int brw  = ((lane >> 4) & 1) * 8 + (lane & 7);
    const int bh8  = ((lane >> 3) & 1) * 8;
    const uint32_t smem_u32 = (uint32_t)__cvta_generic_to_shared(smh);

    float acc[4][4][4];
    #pragma unroll
    for (int mf = 0; mf < 4; mf++)
        #pragma unroll
        for (int nf = 0; nf < 4; nf++)
            #pragma unroll
            for (int r = 0; r < 4; r++) acc[mf][nf][r] = 0.f;

    gemm_issue(smh,         A, Wt, brow, bcol, 0,  tid); CP_COMMIT();
    gemm_issue(smh + STG_H, A, Wt, brow, bcol, 64, tid); CP_COMMIT();

    const int NIT = C_ / 64;   // 16
    #pragma unroll 1
    for (int it = 0; it < NIT; it++) {
        CP_WAIT(1);
        __syncthreads();
        int kn = (it + 2) * 64;
        if (kn < C_) gemm_issue(smh + ((it + 2) % 3) * STG_H, A, Wt, brow, bcol, kn, tid);
        CP_COMMIT();

        uint32_t sbase = smem_u32 + (uint32_t)((it % 3) * STG_H) * 2u;
        uint32_t aaddr = sbase + (uint32_t)((wr * 64 + arow) * SAH + ah8) * 2u;
        uint32_t baddr = sbase + (uint32_t)(128 * SAH) * 2u
                       + (uint32_t)((wc * 32 + brw) * SAH + bh8) * 2u;

        #pragma unroll
        for (int ks = 0; ks < 4; ks++) {
            const int kb = ks * 16;
            uint32_t b0[4], b1[4];
            ldsm4(b0, baddr + (uint32_t)kb * 2u);
            ldsm4(b1, baddr + (uint32_t)(16 * SAH + kb) * 2u);
            #pragma unroll
            for (int mf = 0; mf < 4; mf++) {
                uint32_t a[4];
                ldsm4(a, aaddr + (uint32_t)(mf * 16 * SAH + kb) * 2u);
                mma_f16(acc[mf][0], a[0], a[1], a[2], a[3], b0[0], b0[1]);
                mma_f16(acc[mf][1], a[0], a[1], a[2], a[3], b0[2], b0[3]);
                mma_f16(acc[mf][2], a[0], a[1], a[2], a[3], b1[0], b1[1]);
                mma_f16(acc[mf][3], a[0], a[1], a[2], a[3], b1[2], b1[3]);
            }
        }
    }

    #pragma unroll
    for (int mf = 0; mf < 4; mf++) {
        int row0 = brow + wr * 64 + mf * 16 + lg;
        #pragma unroll
        for (int nf = 0; nf < 4; nf++) {
            int col = bcol + wc * 32 + nf * 8 + lt * 2;
            float bx = bias[col], by = bias[col + 1];
            float v00 = (acc[mf][nf][0] + bx) * sc, v01 = (acc[mf][nf][1] + by) * sc;
            float v10 = (acc[mf][nf][2] + bx) * sc, v11 = (acc[mf][nf][3] + by) * sc;
            if (outHalf) {
                __half* Ch = (__half*)Cm;
                uint32_t o0 = pack_h2(v00, v01), o1 = pack_h2(v10, v11);
                *(uint32_t*)&Ch[(size_t)row0 * C_ + col]       = o0;
                *(uint32_t*)&Ch[(size_t)(row0 + 8) * C_ + col] = o1;
            } else {
                float* Cf = (float*)Cm;
                float2 o0 = { v00, v01 };
                float2 o1 = { v10, v11 };
                *(float2*)&Cf[(size_t)row0 * C_ + col]       = o0;
                *(float2*)&Cf[(size_t)(row0 + 8) * C_ + col] = o1;
            }
        }
    }
}

__global__ __launch_bounds__(256) void qkv_gemm_kernel(
    const float* __restrict__ bq, const float* __restrict__ bk,
    const float* __restrict__ bv)
{
    int sel  = blockIdx.x >> 3;
    int bcol = (blockIdx.x & 7) * 128;
    int brow = blockIdx.y * 128;
    const __half* Wt  = g_wh + ((size_t)sel << 20);
    const float* bias = (sel == 0) ? bq : (sel == 1) ? bk : bv;
    __half* Cm        = (sel == 0) ? g_qh : (sel == 1) ? g_kh : g_vh;
    float sc = (sel == 0) ? 0.125f * 1.4426950408889634f : 1.0f;
    gemm_pipe(g_xh, Wt, bias, Cm, brow, bcol, 1, sc);
}

__global__ __launch_bounds__(256) void out_gemm_kernel(
    const float* __restrict__ bo, float* __restrict__ out)
{
    gemm_pipe(g_oh, g_wh + ((size_t)3 << 20), bo, out,
              blockIdx.y * 128, blockIdx.x * 128, 0, 1.0f);
}

// ---------------------------------------------------------------------------
// FP16 flash attention (m16n8k16), ALiBi + causal.
// 128 thr (4 warps), warp owns 16 query rows, CTA 64 queries.
// K and V both in natural [key][dim] layout; V B-frags via ldmatrix.trans.
// 2-stage cp.async KV; dedicated P region. SMEM 46080B -> 4 CTA/SM.
// ---------------------------------------------------------------------------
#define SKH 72
#define AST_H (128*SKH)                  // 9216 halves per stage (K 64 + V 64 rows)
#define PS_HW (64*SKH)                   // 4608 halves
#define ATT_SMEM ((2*AST_H + PS_HW)*2)   // 46080 bytes

__device__ __forceinline__ void attn_issue_kv(
    __half* stage, int b, int h, int k0, int tid)
{
    __half* Ks = stage;
    __half* Vs = stage + 64 * SKH;
    #pragma unroll
    for (int l = 0; l < 8; l++) {
        int idx = tid + (l << 7);
        int row = idx >> 3;
        int c16 = (idx & 7) << 3;
        if (row < 64)
            cpa16(&Ks[row * SKH + c16],
                  &g_kh[(size_t)(b * T_ + k0 + row) * C_ + h * D_ + c16]);
        else
            cpa16(&Vs[(row - 64) * SKH + c16],
                  &g_vh[(size_t)(b * T_ + k0 + row - 64) * C_ + h * D_ + c16]);
    }
}

__global__ __launch_bounds__(128) void attn_mma_kernel()
{
    extern __shared__ __half smh[];

    const int tid  = threadIdx.x;
    const int lane = tid & 31;
    const int warp = tid >> 5;
    const int lg   = lane >> 2;
    const int lt   = lane & 3;
    const int h    = blockIdx.y;
    const int b    = blockIdx.z;
    const int qbase = (gridDim.x - 1 - blockIdx.x) * 64;   // heavy-first

    const float LOG2E = 1.4426950408889634f;
    const float slope = exp2f(-0.5f * (float)(h + 1)) * LOG2E;

    const int arow = lane & 15;                 // A/P + trans-V row select
    const int ah8  = ((lane >> 4) & 1) * 8;     // A/P + trans-V col select
    const int brw  = ((lane >> 4) & 1) * 8 + (lane & 7);   // non-trans B rows
    const int bh8  = ((lane >> 3) & 1) * 8;
    const uint32_t sm_u32 = (uint32_t)__cvta_generic_to_shared(smh);
    const uint32_t ps_u32 = sm_u32 + (uint32_t)(2 * AST_H) * 2u;

    const int wmin = qbase + warp * 16;
    const int r0 = wmin + lg;

    // Q fragments (Q pre-scaled by 0.125*log2e at projection time).
    uint32_t qf[4][4];
    {
        const __half* q0 = &g_qh[(size_t)(b * T_ + r0) * C_ + h * D_];
        const __half* q1 = q0 + 8 * C_;
        #pragma unroll
        for (int ks = 0; ks < 4; ks++) {
            int c = ks * 16 + 2 * lt;
            qf[ks][0] = *(const uint32_t*)&q0[c];
            qf[ks][1] = *(const uint32_t*)&q1[c];
            qf[ks][2] = *(const uint32_t*)&q0[c + 8];
            qf[ks][3] = *(const uint32_t*)&q1[c + 8];
        }
    }

    float oacc[8][4];
    #pragma unroll
    for (int nf = 0; nf < 8; nf++)
        #pragma unroll
        for (int r = 0; r < 4; r++) oacc[nf][r] = 0.f;
    float m0 = -1e30f, m1 = -1e30f, l0 = 0.f, l1 = 0.f;

    const int ntiles = qbase / 64 + 1;
    __half* Pw = smh + 2 * AST_H + warp * 16 * SKH;
    const uint32_t pw_u32 = ps_u32 + (uint32_t)(warp * 16 * SKH) * 2u;

    attn_issue_kv(smh, b, h, 0, tid); CP_COMMIT();

    #pragma unroll 1
    for (int t = 0; t < ntiles; t++) {
        CP_WAIT(0);
        __syncthreads();
        if (t + 1 < ntiles)
            attn_issue_kv(smh + ((t + 1) & 1) * AST_H, b, h, (t + 1) * 64, tid);
        CP_COMMIT();

        const int k0 = t * 64;
        const uint32_t st_u32 = sm_u32 + (uint32_t)((t & 1) * AST_H) * 2u;
        const uint32_t kaddr  = st_u32 + (uint32_t)(brw * SKH + bh8) * 2u;
        const uint32_t vaddr  = st_u32 + (uint32_t)(64 * SKH) * 2u
                              + (uint32_t)(arow * SKH + ah8) * 2u;   // trans: rows=key

        // S = Q K^T  (16 x 64)
        float s[8][4];
        #pragma unroll
        for (int nf = 0; nf < 8; nf++)
            #pragma unroll
            for (int r = 0; r < 4; r++) s[nf][r] = 0.f;

        #pragma unroll
        for (int ks = 0; ks < 4; ks++) {
            int kb = ks * 16;
            #pragma unroll
            for (int p = 0; p < 4; p++) {
                uint32_t bk[4];
                ldsm4(bk, kaddr + (uint32_t)(p * 16 * SKH + kb) * 2u);
                mma_f16(s[2*p],   qf[ks][0], qf[ks][1], qf[ks][2], qf[ks][3], bk[0], bk[1]);
                mma_f16(s[2*p+1], qf[ks][0], qf[ks][1], qf[ks][2], qf[ks][3], bk[2], bk[3]);
            }
        }

        // ALiBi + causal + row max
        float rmax0 = -1e30f, rmax1 = -1e30f;
        if (k0 + 63 <= wmin) {
            #pragma unroll
            for (int nf = 0; nf < 8; nf++) {
                int kj = k0 + nf * 8 + 2 * lt;
                s[nf][0] += slope * (float)(kj - r0);
                s[nf][1] += slope * (float)(kj + 1 - r0);
                s[nf][2] += slope * (float)(kj - (r0 + 8));
                s[nf][3] += slope * (float)(kj + 1 - (r0 + 8));
                rmax0 = fmaxf(rmax0, fmaxf(s[nf][0], s[nf][1]));
                rmax1 = fmaxf(rmax1, fmaxf(s[nf][2], s[nf][3]));
            }
        } else {
            #pragma unroll
            for (int nf = 0; nf < 8; nf++) {
                int kj = k0 + nf * 8 + 2 * lt;
                int d00 = kj - r0, d01 = kj + 1 - r0;
                int d10 = kj - (r0 + 8), d11 = kj + 1 - (r0 + 8);
                s[nf][0] = (d00 <= 0) ? s[nf][0] + slope * (float)d00 : -1e30f;
                s[nf][1] = (d01 <= 0) ? s[nf][1] + slope * (float)d01 : -1e30f;
                s[nf][2] = (d10 <= 0) ? s[nf][2] + slope * (float)d10 : -1e30f;
                s[nf][3] = (d11 <= 0) ? s[nf][3] + slope * (float)d11 : -1e30f;
                rmax0 = fmaxf(rmax0, fmaxf(s[nf][0], s[nf][1]));
                rmax1 = fmaxf(rmax1, fmaxf(s[nf][2], s[nf][3]));
            }
        }
        rmax0 = fmaxf(rmax0, __shfl_xor_sync(0xffffffffu, rmax0, 1));
        rmax0 = fmaxf(rmax0, __shfl_xor_sync(0xffffffffu, rmax0, 2));
        rmax1 = fmaxf(rmax1, __shfl_xor_sync(0xffffffffu, rmax1, 1));
        rmax1 = fmaxf(rmax1, __shfl_xor_sync(0xffffffffu, rmax1, 2));

        float mn0 = fmaxf(m0, rmax0), mn1 = fmaxf(m1, rmax1);
        float c0 = ex2f(m0 - mn0),  c1 = ex2f(m1 - mn1);
        l0 *= c0; l1 *= c1;
        m0 = mn0; m1 = mn1;

        // P = exp2(S - m) -> SMEM (fp16), row sums
        float rs0 = 0.f, rs1 = 0.f;
        #pragma unroll
        for (int nf = 0; nf < 8; nf++) {
            float p0 = ex2f(s[nf][0] - mn0);
            float p1 = ex2f(s[nf][1] - mn0);
            float p2 = ex2f(s[nf][2] - mn1);
            float p3 = ex2f(s[nf][3] - mn1);
            rs0 += p0 + p1;
            rs1 += p2 + p3;
            int c = nf * 8 + 2 * lt;
            *(uint32_t*)&Pw[lg * SKH + c]       = pack_h2(p0, p1);
            *(uint32_t*)&Pw[(lg + 8) * SKH + c] = pack_h2(p2, p3);
        }
        rs0 += __shfl_xor_sync(0xffffffffu, rs0, 1);
        rs0 += __shfl_xor_sync(0xffffffffu, rs0, 2);
        rs1 += __shfl_xor_sync(0xffffffffu, rs1, 1);
        rs1 += __shfl_xor_sync(0xffffffffu, rs1, 2);
        l0 += rs0; l1 += rs1;

        #pragma unroll
        for (int nf = 0; nf < 8; nf++) {
            oacc[nf][0] *= c0; oacc[nf][1] *= c0;
            oacc[nf][2] *= c1; oacc[nf][3] *= c1;
        }

        __syncwarp();

        // O += P V : A-frags from P (ldmatrix), B-frags from V[key][dim] via ldmatrix.trans
        const uint32_t paddr = pw_u32 + (uint32_t)(arow * SKH + ah8) * 2u;
        #pragma unroll
        for (int ks = 0; ks < 4; ks++) {
            int kb = ks * 16;
            uint32_t a[4];
            ldsm4(a, paddr + (uint32_t)kb * 2u);
            #pragma unroll
            for (int p = 0; p < 4; p++) {
                uint32_t bv[4];
                ldsm4t(bv, vaddr + (uint32_t)(kb * SKH + p * 16) * 2u);
                mma_f16(oacc[2*p],   a[0], a[1], a[2], a[3], bv[0], bv[1]);
                mma_f16(oacc[2*p+1], a[0], a[1], a[2], a[3], bv[2], bv[3]);
            }
        }
    }

    // Final normalize + fp16 store (g_oh feeds fp16 out-proj GEMM).
    float inv0 = 1.f / l0, inv1 = 1.f / l1;
    __half* o0 = &g_oh[(size_t)(b * T_ + r0) * C_ + h * D_];
    __half* o1 = o0 + 8 * C_;
    #pragma unroll
    for (int nf = 0; nf < 8; nf++) {
        int c = nf * 8 + 2 * lt;
        *(uint32_t*)&o0[c] = pack_h2(oacc[nf][0] * inv0, oacc[nf][1] * inv0);
        *(uint32_t*)&o1[c] = pack_h2(oacc[nf][2] * inv1, oacc[nf][3] * inv1);
    }
}

// ---------------------------------------------------------------------------
extern "C" void kernel_launch(void* const* d_in, const int* in_sizes, int n_in,
                              void* d_out, int out_size)
{
    const float* x  = (const float*)d_in[0];
    const float* Wq = (const float*)d_in[1];
    const float* bq = (const float*)d_in[2];
    const float* Wk = (const float*)d_in[3];
    const float* bk = (const float*)d_in[4];
    const float* Wv = (const float*)d_in[5];
    const float* bv = (const float*)d_in[6];
    const float* Wo = (const float*)d_in[7];
    const float* bo = (const float*)d_in[8];
    float* out = (float*)d_out;

    cudaFuncSetAttribute(qkv_gemm_kernel,
                         cudaFuncAttributeMaxDynamicSharedMemorySize, GEMM_SMEM);
    cudaFuncSetAttribute(out_gemm_kernel,
                         cudaFuncAttributeMaxDynamicSharedMemorySize, GEMM_SMEM);
    cudaFuncSetAttribute(attn_mma_kernel,
                         cudaFuncAttributeMaxDynamicSharedMemorySize, ATT_SMEM);

    conv_all_kernel<<<2048, 256>>>(x, Wq, Wk, Wv, Wo);

    qkv_gemm_kernel<<<dim3(24, 32), 256, GEMM_SMEM>>>(bq, bk, bv);

    attn_mma_kernel<<<dim3(T_ / 64, H_, B_), 128, ATT_SMEM>>>();

    out_gemm_kernel<<<dim3(8, 32), 256, GEMM_SMEM>>>(bo, out);
}